// round 1
// baseline (speedup 1.0000x reference)
#include <cuda_runtime.h>
#include <math.h>

#define NT 4096
#define NS 2048
#define NV 1024
#define H 256
#define NH 4
#define DH 64
#define E1 65536
#define E2 16384
#define E3 32768
#define ETOT (2*E1 + E2 + E3)
#define KBIG 1280   // [agg0|agg1|agg2|agg3|x_term] blocks of 256

// ---------------- scratch (static device globals; no allocation) ----------------
__device__ float g_Abig[NT * KBIG];     // 20.97 MB
__device__ float g_cnt[4 * NT];
__device__ float g_Wbig[H * KBIG];      // [Wl0|Wl1|Wl2|Wl3|Wr_sum] per output row
__device__ float g_bsum[H];
__device__ float g_pre[NT * H];         // conv + x_term (pre-LN)
__device__ float g_tout[NT * H];        // term_out (LN output)
__device__ float g_qkv[NT * 3 * H];
__device__ float g_ctx[NT * H];         // attention context (heads concat)
__device__ float g_attn[NT * H];        // after out_proj

// ---------------- weight prep: Wbig + bsum ----------------
__global__ void prep_w_kernel(const float* __restrict__ Wl0, const float* __restrict__ Wl1,
                              const float* __restrict__ Wl2, const float* __restrict__ Wl3,
                              const float* __restrict__ Wr0, const float* __restrict__ Wr1,
                              const float* __restrict__ Wr2, const float* __restrict__ Wr3,
                              const float* __restrict__ bl0, const float* __restrict__ bl1,
                              const float* __restrict__ bl2, const float* __restrict__ bl3)
{
    int idx = blockIdx.x * blockDim.x + threadIdx.x;
    if (idx < H * KBIG) {
        int h = idx / KBIG, c = idx % KBIG;
        int r = c >> 8, k = c & 255;
        int wi = h * H + k;
        float v;
        if (r == 0)      v = Wl0[wi];
        else if (r == 1) v = Wl1[wi];
        else if (r == 2) v = Wl2[wi];
        else if (r == 3) v = Wl3[wi];
        else             v = Wr0[wi] + Wr1[wi] + Wr2[wi] + Wr3[wi];
        g_Wbig[idx] = v;
    }
    if (idx < H) g_bsum[idx] = bl0[idx] + bl1[idx] + bl2[idx] + bl3[idx];
}

// ---------------- init A_big: zero agg blocks, copy x_term to block 4, zero counts ----------------
__global__ void init_A_kernel(const float* __restrict__ xt)
{
    int idx = blockIdx.x * blockDim.x + threadIdx.x;   // float4 index over NT*320
    if (idx < NT * (KBIG / 4)) {
        int n = idx / (KBIG / 4), c4 = idx % (KBIG / 4);
        float4 v;
        if (c4 < 256) v = make_float4(0.f, 0.f, 0.f, 0.f);
        else          v = *((const float4*)(xt + (size_t)n * H) + (c4 - 256));
        ((float4*)g_Abig)[idx] = v;
    }
    if (idx < 4 * NT) g_cnt[idx] = 0.f;
}

// ---------------- edge degree counts ----------------
__global__ void count_kernel(const int* __restrict__ ha_src, const int* __restrict__ ha_dst,
                             const int* __restrict__ so_src, const int* __restrict__ so_dst,
                             const int* __restrict__ vo_src, const int* __restrict__ vo_dst)
{
    int e = blockIdx.x * blockDim.x + threadIdx.x;
    if (e >= ETOT) return;
    int r, d;
    if (e < E1)               { r = 0; d = ha_src[e]; }
    else if (e < 2 * E1)      { r = 1; d = ha_dst[e - E1]; }
    else if (e < 2 * E1 + E2) { r = 2; d = so_src[e - 2 * E1]; }
    else                      { r = 3; d = vo_dst[e - 2 * E1 - E2]; }
    atomicAdd(&g_cnt[r * NT + d], 1.f);
}

// ---------------- scatter-add messages (vector red) ----------------
__global__ void scatter_kernel(const float* __restrict__ xt, const float* __restrict__ xs,
                               const float* __restrict__ xv,
                               const int* __restrict__ ha_src, const int* __restrict__ ha_dst,
                               const int* __restrict__ so_src, const int* __restrict__ so_dst,
                               const int* __restrict__ vo_src, const int* __restrict__ vo_dst)
{
    int idx = blockIdx.x * blockDim.x + threadIdx.x;
    if (idx >= ETOT * 64) return;
    int e = idx >> 6, j = idx & 63;
    int r, s, d; const float* x;
    if (e < E1)               { r = 0; s = ha_dst[e];            d = ha_src[e];            x = xt; }
    else if (e < 2 * E1)      { int q = e - E1;          r = 1; s = ha_src[q]; d = ha_dst[q]; x = xt; }
    else if (e < 2 * E1 + E2) { int q = e - 2 * E1;      r = 2; s = so_dst[q]; d = so_src[q]; x = xs; }
    else                      { int q = e - 2 * E1 - E2; r = 3; s = vo_src[q]; d = vo_dst[q]; x = xv; }
    float4 v = *((const float4*)(x + (size_t)s * H) + j);
    float* p = g_Abig + (size_t)d * KBIG + r * H + j * 4;
    asm volatile("red.global.add.v4.f32 [%0], {%1,%2,%3,%4};"
                 :: "l"(p), "f"(v.x), "f"(v.y), "f"(v.z), "f"(v.w) : "memory");
}

// ---------------- mean: divide agg blocks by count ----------------
__global__ void scale_kernel()
{
    int idx = blockIdx.x * blockDim.x + threadIdx.x;   // float4 index over first 1024 cols
    if (idx >= NT * 256) return;
    int n = idx >> 8, c4 = idx & 255;
    int r = c4 >> 6;
    float inv = 1.f / fmaxf(g_cnt[r * NT + n], 1.f);
    float4* p = (float4*)(g_Abig + (size_t)n * KBIG) + c4;
    float4 v = *p;
    v.x *= inv; v.y *= inv; v.z *= inv; v.w *= inv;
    *p = v;
}

// ---------------- generic GEMM: C[M,N] = A[M,K] @ W[N,K]^T + bias (+epilogue) ----------------
// mode 0: +bias ; mode 1: +bias+resid ; mode 2: relu(+bias)+resid
#define GBM 64
#define GBN 64
#define GBK 16
__global__ __launch_bounds__(128)
void gemm_kernel(const float* __restrict__ A, const float* __restrict__ W,
                 const float* __restrict__ bias, const float* __restrict__ resid,
                 float* __restrict__ C, int M, int N, int K, int mode)
{
    __shared__ __align__(16) float As[GBM][GBK + 1];
    __shared__ __align__(16) float Bs[GBK][GBN + 4];
    int tid = threadIdx.x;
    int ry = tid >> 4;     // 0..7 -> rows ry*8..+7
    int cx = tid & 15;     // cols cx*4..+3
    int rb = blockIdx.y * GBM;
    int cb = blockIdx.x * GBN;

    float acc[8][4];
#pragma unroll
    for (int j = 0; j < 8; j++)
#pragma unroll
        for (int i = 0; i < 4; i++) acc[j][i] = 0.f;

    for (int kb = 0; kb < K; kb += GBK) {
#pragma unroll
        for (int p = tid; p < 256; p += 128) {
            int r = p >> 2, k4 = p & 3;
            float4 v = *(const float4*)(A + (size_t)(rb + r) * K + kb + k4 * 4);
            As[r][k4 * 4 + 0] = v.x; As[r][k4 * 4 + 1] = v.y;
            As[r][k4 * 4 + 2] = v.z; As[r][k4 * 4 + 3] = v.w;
        }
#pragma unroll
        for (int p = tid; p < 256; p += 128) {
            int c = p >> 2, k4 = p & 3;
            float4 v = *(const float4*)(W + (size_t)(cb + c) * K + kb + k4 * 4);
            Bs[k4 * 4 + 0][c] = v.x; Bs[k4 * 4 + 1][c] = v.y;
            Bs[k4 * 4 + 2][c] = v.z; Bs[k4 * 4 + 3][c] = v.w;
        }
        __syncthreads();
#pragma unroll
        for (int kk = 0; kk < GBK; kk++) {
            float a[8];
#pragma unroll
            for (int j = 0; j < 8; j++) a[j] = As[ry * 8 + j][kk];
            float4 b = *(const float4*)&Bs[kk][cx * 4];
#pragma unroll
            for (int j = 0; j < 8; j++) {
                acc[j][0] += a[j] * b.x; acc[j][1] += a[j] * b.y;
                acc[j][2] += a[j] * b.z; acc[j][3] += a[j] * b.w;
            }
        }
        __syncthreads();
    }

    float4 bv = *(const float4*)(bias + cb + cx * 4);
#pragma unroll
    for (int j = 0; j < 8; j++) {
        int row = rb + ry * 8 + j;
        float4 v = make_float4(acc[j][0] + bv.x, acc[j][1] + bv.y,
                               acc[j][2] + bv.z, acc[j][3] + bv.w);
        if (mode == 2) {
            v.x = fmaxf(v.x, 0.f); v.y = fmaxf(v.y, 0.f);
            v.z = fmaxf(v.z, 0.f); v.w = fmaxf(v.w, 0.f);
        }
        if (mode >= 1) {
            float4 rr = *(const float4*)(resid + (size_t)row * N + cb + cx * 4);
            v.x += rr.x; v.y += rr.y; v.z += rr.z; v.w += rr.w;
        }
        *(float4*)(C + (size_t)row * N + cb + cx * 4) = v;
    }
}

// ---------------- layernorm (one warp per row) ----------------
__global__ __launch_bounds__(256)
void ln_kernel(const float* __restrict__ pre, const float* __restrict__ gam,
               const float* __restrict__ bet, float* __restrict__ out)
{
    int row = blockIdx.x * 8 + (threadIdx.x >> 5);
    int lane = threadIdx.x & 31;
    const float* p = pre + (size_t)row * H + lane * 8;
    float4 a = *(const float4*)p;
    float4 b = *(const float4*)(p + 4);
    float s = a.x + a.y + a.z + a.w + b.x + b.y + b.z + b.w;
#pragma unroll
    for (int off = 16; off; off >>= 1) s += __shfl_xor_sync(0xffffffffu, s, off);
    float mu = s * (1.f / H);
    float dx[8] = {a.x - mu, a.y - mu, a.z - mu, a.w - mu, b.x - mu, b.y - mu, b.z - mu, b.w - mu};
    float vs = 0.f;
#pragma unroll
    for (int i = 0; i < 8; i++) vs += dx[i] * dx[i];
#pragma unroll
    for (int off = 16; off; off >>= 1) vs += __shfl_xor_sync(0xffffffffu, vs, off);
    float rstd = rsqrtf(vs * (1.f / H) + 1e-5f);
    float4 g0 = *(const float4*)(gam + lane * 8);
    float4 g1 = *(const float4*)(gam + lane * 8 + 4);
    float4 b0 = *(const float4*)(bet + lane * 8);
    float4 b1 = *(const float4*)(bet + lane * 8 + 4);
    float4 o0 = make_float4(dx[0] * rstd * g0.x + b0.x, dx[1] * rstd * g0.y + b0.y,
                            dx[2] * rstd * g0.z + b0.z, dx[3] * rstd * g0.w + b0.w);
    float4 o1 = make_float4(dx[4] * rstd * g1.x + b1.x, dx[5] * rstd * g1.y + b1.y,
                            dx[6] * rstd * g1.z + b1.z, dx[7] * rstd * g1.w + b1.w);
    float* q = out + (size_t)row * H + lane * 8;
    *(float4*)q = o0;
    *(float4*)(q + 4) = o1;
}

// ---------------- flash attention (fp32 SIMT), 4 heads, D=64, N=4096 ----------------
#define AT_SROW 68
#define ATTN_SMEM (4 * 64 * AT_SROW * 4)
__global__ __launch_bounds__(256)
void attn_kernel(const float* __restrict__ qkv, float* __restrict__ ctx)
{
    extern __shared__ __align__(16) float sm[];
    float* Qs = sm;
    float* Ks = sm + 64 * AT_SROW;
    float* Vs = sm + 2 * 64 * AT_SROW;
    float* Ps = sm + 3 * 64 * AT_SROW;

    int tid = threadIdx.x;
    int qy = tid >> 4;   // 0..15, q rows qy*4..+3
    int cx = tid & 15;   // S cols {cx,cx+16,cx+32,cx+48}; O cols cx*4..+3
    int h = blockIdx.y;
    int q0 = blockIdx.x * 64;

    for (int p = tid; p < 1024; p += 256) {
        int r = p >> 4, d4 = p & 15;
        *(float4*)(Qs + r * AT_SROW + d4 * 4) =
            *(const float4*)(qkv + (size_t)(q0 + r) * 768 + h * 64 + d4 * 4);
    }

    float m[4], l[4], o[4][4];
#pragma unroll
    for (int j = 0; j < 4; j++) {
        m[j] = -1e30f; l[j] = 0.f;
#pragma unroll
        for (int i = 0; i < 4; i++) o[j][i] = 0.f;
    }

    for (int kt = 0; kt < 64; kt++) {
        int k0 = kt * 64;
        for (int p = tid; p < 1024; p += 256) {
            int r = p >> 4, d4 = p & 15;
            const float* base = qkv + (size_t)(k0 + r) * 768 + h * 64 + d4 * 4;
            *(float4*)(Ks + r * AT_SROW + d4 * 4) = *(const float4*)(base + 256);
            *(float4*)(Vs + r * AT_SROW + d4 * 4) = *(const float4*)(base + 512);
        }
        __syncthreads();

        float s[4][4];
#pragma unroll
        for (int j = 0; j < 4; j++)
#pragma unroll
            for (int i = 0; i < 4; i++) s[j][i] = 0.f;

#pragma unroll
        for (int d4 = 0; d4 < 16; d4++) {
            float4 kv[4];
#pragma unroll
            for (int i = 0; i < 4; i++)
                kv[i] = *(const float4*)(Ks + (cx + 16 * i) * AT_SROW + d4 * 4);
#pragma unroll
            for (int j = 0; j < 4; j++) {
                float4 qv = *(const float4*)(Qs + (qy * 4 + j) * AT_SROW + d4 * 4);
#pragma unroll
                for (int i = 0; i < 4; i++)
                    s[j][i] += qv.x * kv[i].x + qv.y * kv[i].y + qv.z * kv[i].z + qv.w * kv[i].w;
            }
        }

#pragma unroll
        for (int j = 0; j < 4; j++) {
            float mx = -1e30f;
#pragma unroll
            for (int i = 0; i < 4; i++) { s[j][i] *= 0.125f; mx = fmaxf(mx, s[j][i]); }
#pragma unroll
            for (int off = 1; off < 16; off <<= 1)
                mx = fmaxf(mx, __shfl_xor_sync(0xffffffffu, mx, off));
            float mn = fmaxf(m[j], mx);
            float al = __expf(m[j] - mn);
            m[j] = mn;
            float rs = 0.f;
#pragma unroll
            for (int i = 0; i < 4; i++) { s[j][i] = __expf(s[j][i] - mn); rs += s[j][i]; }
#pragma unroll
            for (int off = 1; off < 16; off <<= 1)
                rs += __shfl_xor_sync(0xffffffffu, rs, off);
            l[j] = l[j] * al + rs;
#pragma unroll
            for (int i = 0; i < 4; i++) o[j][i] *= al;
#pragma unroll
            for (int i = 0; i < 4; i++) Ps[(qy * 4 + j) * AT_SROW + cx + 16 * i] = s[j][i];
        }
        __syncthreads();

#pragma unroll 8
        for (int c = 0; c < 64; c++) {
            float4 vv = *(const float4*)(Vs + c * AT_SROW + cx * 4);
#pragma unroll
            for (int j = 0; j < 4; j++) {
                float pv = Ps[(qy * 4 + j) * AT_SROW + c];
                o[j][0] += pv * vv.x; o[j][1] += pv * vv.y;
                o[j][2] += pv * vv.z; o[j][3] += pv * vv.w;
            }
        }
        __syncthreads();
    }

#pragma unroll
    for (int j = 0; j < 4; j++) {
        float inv = 1.f / l[j];
        int row = q0 + qy * 4 + j;
        float4 v = make_float4(o[j][0] * inv, o[j][1] * inv, o[j][2] * inv, o[j][3] * inv);
        *(float4*)(ctx + (size_t)row * 256 + h * 64 + cx * 4) = v;
    }
}

// ---------------- launch ----------------
extern "C" void kernel_launch(void* const* d_in, const int* in_sizes, int n_in,
                              void* d_out, int out_size)
{
    (void)in_sizes; (void)n_in; (void)out_size;
    const float* x_term    = (const float*)d_in[0];
    const float* x_symbol  = (const float*)d_in[1];
    const float* x_var     = (const float*)d_in[2];
    const int*   ha_src    = (const int*)d_in[3];
    const int*   ha_dst    = (const int*)d_in[4];
    const int*   so_src    = (const int*)d_in[5];
    const int*   so_dst    = (const int*)d_in[6];
    const int*   vo_src    = (const int*)d_in[7];
    const int*   vo_dst    = (const int*)d_in[8];
    const float* Wl_rha    = (const float*)d_in[9];
    const float* bl_rha    = (const float*)d_in[10];
    const float* Wr_rha    = (const float*)d_in[11];
    const float* Wl_ha     = (const float*)d_in[12];
    const float* bl_ha     = (const float*)d_in[13];
    const float* Wr_ha     = (const float*)d_in[14];
    const float* Wl_rsym   = (const float*)d_in[15];
    const float* bl_rsym   = (const float*)d_in[16];
    const float* Wr_rsym   = (const float*)d_in[17];
    const float* Wl_var    = (const float*)d_in[18];
    const float* bl_var    = (const float*)d_in[19];
    const float* Wr_var    = (const float*)d_in[20];
    const float* ln_g      = (const float*)d_in[21];
    const float* ln_b      = (const float*)d_in[22];
    const float* in_proj_w = (const float*)d_in[23];
    const float* in_proj_b = (const float*)d_in[24];
    const float* out_proj_w= (const float*)d_in[25];
    const float* out_proj_b= (const float*)d_in[26];
    const float* post_w    = (const float*)d_in[27];
    const float* post_b    = (const float*)d_in[28];
    float* out = (float*)d_out;

    cudaFuncSetAttribute(attn_kernel, cudaFuncAttributeMaxDynamicSharedMemorySize, ATTN_SMEM);

    float *pAbig, *pWbig, *pbsum, *ppre, *ptout, *pqkv, *pctx, *pattn;
    cudaGetSymbolAddress((void**)&pAbig, g_Abig);
    cudaGetSymbolAddress((void**)&pWbig, g_Wbig);
    cudaGetSymbolAddress((void**)&pbsum, g_bsum);
    cudaGetSymbolAddress((void**)&ppre,  g_pre);
    cudaGetSymbolAddress((void**)&ptout, g_tout);
    cudaGetSymbolAddress((void**)&pqkv,  g_qkv);
    cudaGetSymbolAddress((void**)&pctx,  g_ctx);
    cudaGetSymbolAddress((void**)&pattn, g_attn);

    prep_w_kernel<<<(H * KBIG + 255) / 256, 256>>>(Wl_rha, Wl_ha, Wl_rsym, Wl_var,
                                                   Wr_rha, Wr_ha, Wr_rsym, Wr_var,
                                                   bl_rha, bl_ha, bl_rsym, bl_var);
    init_A_kernel<<<(NT * (KBIG / 4) + 255) / 256, 256>>>(x_term);
    count_kernel<<<(ETOT + 255) / 256, 256>>>(ha_src, ha_dst, so_src, so_dst, vo_src, vo_dst);
    scatter_kernel<<<(ETOT * 64 + 255) / 256, 256>>>(x_term, x_symbol, x_var,
                                                     ha_src, ha_dst, so_src, so_dst, vo_src, vo_dst);
    scale_kernel<<<(NT * 256 + 255) / 256, 256>>>();

    // conv = A_big @ Wbig^T + bsum + x_term (residual)  -> g_pre
    gemm_kernel<<<dim3(H / GBN, NT / GBM), 128>>>(pAbig, pWbig, pbsum, x_term, ppre,
                                                  NT, H, KBIG, 1);
    // layernorm -> g_tout
    ln_kernel<<<NT / 8, 256>>>(ppre, ln_g, ln_b, ptout);
    // qkv
    gemm_kernel<<<dim3(3 * H / GBN, NT / GBM), 128>>>(ptout, in_proj_w, in_proj_b, nullptr, pqkv,
                                                      NT, 3 * H, H, 0);
    // attention
    attn_kernel<<<dim3(NT / 64, NH), 256, ATTN_SMEM>>>(pqkv, pctx);
    // out_proj
    gemm_kernel<<<dim3(H / GBN, NT / GBM), 128>>>(pctx, out_proj_w, out_proj_b, nullptr, pattn,
                                                  NT, H, H, 0);
    // post: relu(attn @ post_w^T + post_b) + term_out -> d_out
    gemm_kernel<<<dim3(H / GBN, NT / GBM), 128>>>(pattn, post_w, post_b, ptout, out,
                                                  NT, H, H, 2);
}

// round 4
// speedup vs baseline: 1.4728x; 1.4728x over previous
#include <cuda_runtime.h>
#include <math.h>
#include <cstdint>

#define NT 4096
#define NS 2048
#define NV 1024
#define H 256
#define NH 4
#define DH 64
#define E1 65536
#define E2 16384
#define E3 32768
#define ETOT (2*E1 + E2 + E3)
#define KBIG 1280   // [agg0|agg1|agg2|agg3|x_term] blocks of 256

// ---------------- scratch (static device globals; no allocation) ----------------
__device__ float g_Abig[NT * KBIG];
__device__ float g_cnt[4 * NT];
__device__ float g_Wbig[H * KBIG];
__device__ float g_bsum[H];
__device__ float g_pre[NT * H];
__device__ float g_tout[NT * H];
__device__ float g_qkv[NT * 3 * H];
__device__ float g_ctx[NT * H];
__device__ float g_attn[NT * H];

// ---------------- mma.sync tf32 helper ----------------
__device__ __forceinline__ void mma_tf32(float* c, uint32_t a0, uint32_t a1, uint32_t a2, uint32_t a3,
                                         uint32_t b0, uint32_t b1)
{
    asm volatile("mma.sync.aligned.m16n8k8.row.col.f32.tf32.tf32.f32 "
                 "{%0,%1,%2,%3},{%4,%5,%6,%7},{%8,%9},{%0,%1,%2,%3};"
                 : "+f"(c[0]), "+f"(c[1]), "+f"(c[2]), "+f"(c[3])
                 : "r"(a0), "r"(a1), "r"(a2), "r"(a3), "r"(b0), "r"(b1));
}
// interleaved store of one 8-col group: positions (c0,c4,c1,c5)(c2,c6,c3,c7)
// => fragment cols (tig, tig+4) become an adjacent float2 at offset 2*tig.
__device__ __forceinline__ void sts_perm8(float* dst, float4 A0, float4 A1)
{
    *(float4*)dst       = make_float4(A0.x, A1.x, A0.y, A1.y);
    *(float4*)(dst + 4) = make_float4(A0.z, A1.z, A0.w, A1.w);
}
__device__ __forceinline__ float tf32_mask(float x) {
    return __uint_as_float(__float_as_uint(x) & 0xffffe000u);
}

// ---------------- weight prep ----------------
__global__ void prep_w_kernel(const float* __restrict__ Wl0, const float* __restrict__ Wl1,
                              const float* __restrict__ Wl2, const float* __restrict__ Wl3,
                              const float* __restrict__ Wr0, const float* __restrict__ Wr1,
                              const float* __restrict__ Wr2, const float* __restrict__ Wr3,
                              const float* __restrict__ bl0, const float* __restrict__ bl1,
                              const float* __restrict__ bl2, const float* __restrict__ bl3)
{
    int idx = blockIdx.x * blockDim.x + threadIdx.x;
    if (idx < H * KBIG) {
        int h = idx / KBIG, c = idx % KBIG;
        int r = c >> 8, k = c & 255;
        int wi = h * H + k;
        float v;
        if (r == 0)      v = Wl0[wi];
        else if (r == 1) v = Wl1[wi];
        else if (r == 2) v = Wl2[wi];
        else if (r == 3) v = Wl3[wi];
        else             v = Wr0[wi] + Wr1[wi] + Wr2[wi] + Wr3[wi];
        g_Wbig[idx] = v;
    }
    if (idx < H) g_bsum[idx] = bl0[idx] + bl1[idx] + bl2[idx] + bl3[idx];
}

__global__ void init_A_kernel(const float* __restrict__ xt)
{
    int idx = blockIdx.x * blockDim.x + threadIdx.x;
    if (idx < NT * (KBIG / 4)) {
        int n = idx / (KBIG / 4), c4 = idx % (KBIG / 4);
        float4 v;
        if (c4 < 256) v = make_float4(0.f, 0.f, 0.f, 0.f);
        else          v = *((const float4*)(xt + (size_t)n * H) + (c4 - 256));
        ((float4*)g_Abig)[idx] = v;
    }
    if (idx < 4 * NT) g_cnt[idx] = 0.f;
}

__global__ void count_kernel(const int* __restrict__ ha_src, const int* __restrict__ ha_dst,
                             const int* __restrict__ so_src, const int* __restrict__ so_dst,
                             const int* __restrict__ vo_src, const int* __restrict__ vo_dst)
{
    int e = blockIdx.x * blockDim.x + threadIdx.x;
    if (e >= ETOT) return;
    int r, d;
    if (e < E1)               { r = 0; d = ha_src[e]; }
    else if (e < 2 * E1)      { r = 1; d = ha_dst[e - E1]; }
    else if (e < 2 * E1 + E2) { r = 2; d = so_src[e - 2 * E1]; }
    else                      { r = 3; d = vo_dst[e - 2 * E1 - E2]; }
    atomicAdd(&g_cnt[r * NT + d], 1.f);
}

__global__ void scatter_kernel(const float* __restrict__ xt, const float* __restrict__ xs,
                               const float* __restrict__ xv,
                               const int* __restrict__ ha_src, const int* __restrict__ ha_dst,
                               const int* __restrict__ so_src, const int* __restrict__ so_dst,
                               const int* __restrict__ vo_src, const int* __restrict__ vo_dst)
{
    int idx = blockIdx.x * blockDim.x + threadIdx.x;
    if (idx >= ETOT * 64) return;
    int e = idx >> 6, j = idx & 63;
    int r, s, d; const float* x;
    if (e < E1)               { r = 0; s = ha_dst[e];            d = ha_src[e];            x = xt; }
    else if (e < 2 * E1)      { int q = e - E1;          r = 1; s = ha_src[q]; d = ha_dst[q]; x = xt; }
    else if (e < 2 * E1 + E2) { int q = e - 2 * E1;      r = 2; s = so_dst[q]; d = so_src[q]; x = xs; }
    else                      { int q = e - 2 * E1 - E2; r = 3; s = vo_src[q]; d = vo_dst[q]; x = xv; }
    float4 v = *((const float4*)(x + (size_t)s * H) + j);
    float* p = g_Abig + (size_t)d * KBIG + r * H + j * 4;
    asm volatile("red.global.add.v4.f32 [%0], {%1,%2,%3,%4};"
                 :: "l"(p), "f"(v.x), "f"(v.y), "f"(v.z), "f"(v.w) : "memory");
}

__global__ void scale_kernel()
{
    int idx = blockIdx.x * blockDim.x + threadIdx.x;
    if (idx >= NT * 256) return;
    int n = idx >> 8, c4 = idx & 255;
    int r = c4 >> 6;
    float inv = 1.f / fmaxf(g_cnt[r * NT + n], 1.f);
    float4* p = (float4*)(g_Abig + (size_t)n * KBIG) + c4;
    float4 v = *p;
    v.x *= inv; v.y *= inv; v.z *= inv; v.w *= inv;
    *p = v;
}

// ================= tf32 tensor-core GEMM =================
// C[M,N] = A[M,K] @ W[N,K]^T + bias (+epilogue). M%128==0, N%64==0, K%32==0.
// CTA: 128 threads (4 warps), tile 128x64. Warp w: rows 32w..32w+31 (2 m-tiles).
// k-chunk 32, register-prefetch pipeline. Permuted k-columns in smem (pair-interleave
// per 8-group) so A/B fragments are single LDS.64. Row stride 40 (=8 mod 32): conflict-free.
#define GS 40
__global__ __launch_bounds__(128, 1)
void gemm_tc_kernel(const float* __restrict__ A, const float* __restrict__ W,
                    const float* __restrict__ bias, const float* __restrict__ resid,
                    float* __restrict__ C, int M, int N, int K, int mode)
{
    __shared__ __align__(16) float As[128 * GS];
    __shared__ __align__(16) float Ws[64 * GS];
    int tid = threadIdx.x;
    int lane = tid & 31, wid = tid >> 5;
    int g = lane >> 2, tig = lane & 3;
    int rb = blockIdx.y * 128;
    int cb = blockIdx.x * 64;

    int aRow = tid;                 // A load: 1 row, 32 cols
    int wRow = tid >> 1;            // W load: row, half = 16 cols
    int wHalf = (tid & 1) * 16;

    float4 aR[8], wR[4];
    const float* Ap = A + (size_t)(rb + aRow) * K;
    const float* Wp = W + (size_t)(cb + wRow) * K + wHalf;

    // prologue: prefetch chunk 0
#pragma unroll
    for (int j = 0; j < 8; j++) aR[j] = *(const float4*)(Ap + j * 4);
#pragma unroll
    for (int j = 0; j < 4; j++) wR[j] = *(const float4*)(Wp + j * 4);

    float acc[2][8][4];
#pragma unroll
    for (int m = 0; m < 2; m++)
#pragma unroll
        for (int n = 0; n < 8; n++)
#pragma unroll
            for (int i = 0; i < 4; i++) acc[m][n][i] = 0.f;

    int nchunk = K >> 5;
    for (int kc = 0; kc < nchunk; kc++) {
        // store prefetched chunk (permuted)
#pragma unroll
        for (int j2 = 0; j2 < 4; j2++)
            sts_perm8(As + aRow * GS + j2 * 8, aR[2 * j2], aR[2 * j2 + 1]);
#pragma unroll
        for (int j2 = 0; j2 < 2; j2++)
            sts_perm8(Ws + wRow * GS + wHalf + j2 * 8, wR[2 * j2], wR[2 * j2 + 1]);
        __syncthreads();

        if (kc + 1 < nchunk) {
            const float* Ap2 = Ap + (kc + 1) * 32;
            const float* Wp2 = Wp + (kc + 1) * 32;
#pragma unroll
            for (int j = 0; j < 8; j++) aR[j] = *(const float4*)(Ap2 + j * 4);
#pragma unroll
            for (int j = 0; j < 4; j++) wR[j] = *(const float4*)(Wp2 + j * 4);
        }

#pragma unroll
        for (int k4 = 0; k4 < 4; k4++) {
            int kk = k4 * 8;
            float2 a0m[2], a1m[2];
#pragma unroll
            for (int m = 0; m < 2; m++) {
                int r0 = wid * 32 + m * 16 + g;
                a0m[m] = *(float2*)&As[r0 * GS + kk + 2 * tig];
                a1m[m] = *(float2*)&As[(r0 + 8) * GS + kk + 2 * tig];
            }
#pragma unroll
            for (int n = 0; n < 8; n++) {
                float2 b = *(float2*)&Ws[(n * 8 + g) * GS + kk + 2 * tig];
                uint32_t b0 = __float_as_uint(b.x), b1 = __float_as_uint(b.y);
#pragma unroll
                for (int m = 0; m < 2; m++)
                    mma_tf32(acc[m][n],
                             __float_as_uint(a0m[m].x), __float_as_uint(a1m[m].x),
                             __float_as_uint(a0m[m].y), __float_as_uint(a1m[m].y),
                             b0, b1);
            }
        }
        __syncthreads();
    }

    // epilogue
#pragma unroll
    for (int m = 0; m < 2; m++) {
        int r0 = rb + wid * 32 + m * 16 + g;
#pragma unroll
        for (int n = 0; n < 8; n++) {
            int col = cb + n * 8 + 2 * tig;
            float2 bv = *(const float2*)(bias + col);
            float2 v0 = make_float2(acc[m][n][0] + bv.x, acc[m][n][1] + bv.y);
            float2 v1 = make_float2(acc[m][n][2] + bv.x, acc[m][n][3] + bv.y);
            if (mode == 2) {
                v0.x = fmaxf(v0.x, 0.f); v0.y = fmaxf(v0.y, 0.f);
                v1.x = fmaxf(v1.x, 0.f); v1.y = fmaxf(v1.y, 0.f);
            }
            if (mode >= 1) {
                float2 r0v = *(const float2*)(resid + (size_t)r0 * N + col);
                float2 r1v = *(const float2*)(resid + (size_t)(r0 + 8) * N + col);
                v0.x += r0v.x; v0.y += r0v.y; v1.x += r1v.x; v1.y += r1v.y;
            }
            *(float2*)(C + (size_t)r0 * N + col) = v0;
            *(float2*)(C + (size_t)(r0 + 8) * N + col) = v1;
        }
    }
}

// ---------------- layernorm ----------------
__global__ __launch_bounds__(256)
void ln_kernel(const float* __restrict__ pre, const float* __restrict__ gam,
               const float* __restrict__ bet, float* __restrict__ out)
{
    int row = blockIdx.x * 8 + (threadIdx.x >> 5);
    int lane = threadIdx.x & 31;
    const float* p = pre + (size_t)row * H + lane * 8;
    float4 a = *(const float4*)p;
    float4 b = *(const float4*)(p + 4);
    float s = a.x + a.y + a.z + a.w + b.x + b.y + b.z + b.w;
#pragma unroll
    for (int off = 16; off; off >>= 1) s += __shfl_xor_sync(0xffffffffu, s, off);
    float mu = s * (1.f / H);
    float dx[8] = {a.x - mu, a.y - mu, a.z - mu, a.w - mu, b.x - mu, b.y - mu, b.z - mu, b.w - mu};
    float vs = 0.f;
#pragma unroll
    for (int i = 0; i < 8; i++) vs += dx[i] * dx[i];
#pragma unroll
    for (int off = 16; off; off >>= 1) vs += __shfl_xor_sync(0xffffffffu, vs, off);
    float rstd = rsqrtf(vs * (1.f / H) + 1e-5f);
    float4 g0 = *(const float4*)(gam + lane * 8);
    float4 g1 = *(const float4*)(gam + lane * 8 + 4);
    float4 b0 = *(const float4*)(bet + lane * 8);
    float4 b1 = *(const float4*)(bet + lane * 8 + 4);
    float4 o0 = make_float4(dx[0] * rstd * g0.x + b0.x, dx[1] * rstd * g0.y + b0.y,
                            dx[2] * rstd * g0.z + b0.z, dx[3] * rstd * g0.w + b0.w);
    float4 o1 = make_float4(dx[4] * rstd * g1.x + b1.x, dx[5] * rstd * g1.y + b1.y,
                            dx[6] * rstd * g1.z + b1.z, dx[7] * rstd * g1.w + b1.w);
    float* q = out + (size_t)row * H + lane * 8;
    *(float4*)q = o0;
    *(float4*)(q + 4) = o1;
}

// ================= tf32 mma.sync flash attention =================
// CTA: 128 threads (4 warps), 128 q-rows, one head. Key tiles of 64.
// Fixed-shift softmax (scores bounded): P = exp(s/8), l accumulated, O normalized at end.
// smem: Qs[128][72], Ks[64][72] (permuted d-cols), VTs[64][72] (V^T, permuted key-cols).
#define AS 72
#define ATTN_SMEM_BYTES ((128 + 64 + 64) * AS * 4)

__global__ __launch_bounds__(128, 1)
void attn_tc_kernel(const float* __restrict__ qkv, float* __restrict__ ctx)
{
    extern __shared__ __align__(16) float sm[];
    float* Qs  = sm;
    float* Ks  = sm + 128 * AS;
    float* VTs = Ks + 64 * AS;

    int tid = threadIdx.x;
    int lane = tid & 31, wid = tid >> 5;
    int g = lane >> 2, tig = lane & 3;
    int h = blockIdx.y;
    int q0 = blockIdx.x * 128;

    // ---- load Q (once), permuted d-columns ----
    {
        const float* qr = qkv + (size_t)(q0 + tid) * 768 + h * 64;
#pragma unroll
        for (int j2 = 0; j2 < 8; j2++) {
            float4 A0 = *(const float4*)(qr + j2 * 8);
            float4 A1 = *(const float4*)(qr + j2 * 8 + 4);
            sts_perm8(Qs + tid * AS + j2 * 8, A0, A1);
        }
    }

    // K/V prefetch: thread covers K row r = tid>>1, 32-col half.
    int kRow = tid >> 1;
    int kHalf = (tid & 1) * 32;
    int vpos = (kRow & ~7) | (2 * (kRow & 3)) | ((kRow >> 2) & 1);  // permuted key position
    float4 Kbuf[8], Vbuf[8];
    {
        const float* kp = qkv + (size_t)kRow * 768 + 256 + h * 64 + kHalf;
#pragma unroll
        for (int j = 0; j < 8; j++) Kbuf[j] = *(const float4*)(kp + j * 4);
#pragma unroll
        for (int j = 0; j < 8; j++) Vbuf[j] = *(const float4*)(kp + 256 + j * 4);
    }

    float O[2][8][4];
#pragma unroll
    for (int m = 0; m < 2; m++)
#pragma unroll
        for (int n = 0; n < 8; n++)
#pragma unroll
            for (int i = 0; i < 4; i++) O[m][n][i] = 0.f;
    float lacc[2][2] = {{0.f, 0.f}, {0.f, 0.f}};

    for (int kt = 0; kt < 64; kt++) {
        // store prefetched K (permuted d-cols) and V^T (permuted key-cols)
#pragma unroll
        for (int j2 = 0; j2 < 4; j2++)
            sts_perm8(Ks + kRow * AS + kHalf + j2 * 8, Kbuf[2 * j2], Kbuf[2 * j2 + 1]);
#pragma unroll
        for (int j = 0; j < 8; j++) {
            int d = kHalf + j * 4;
            VTs[(d + 0) * AS + vpos] = Vbuf[j].x;
            VTs[(d + 1) * AS + vpos] = Vbuf[j].y;
            VTs[(d + 2) * AS + vpos] = Vbuf[j].z;
            VTs[(d + 3) * AS + vpos] = Vbuf[j].w;
        }
        __syncthreads();

        if (kt + 1 < 64) {
            const float* kp = qkv + (size_t)((kt + 1) * 64 + kRow) * 768 + 256 + h * 64 + kHalf;
#pragma unroll
            for (int j = 0; j < 8; j++) Kbuf[j] = *(const float4*)(kp + j * 4);
#pragma unroll
            for (int j = 0; j < 8; j++) Vbuf[j] = *(const float4*)(kp + 256 + j * 4);
        }

#pragma unroll
        for (int m = 0; m < 2; m++) {
            int qr = wid * 32 + m * 16 + g;
            float c[8][4];
#pragma unroll
            for (int n = 0; n < 8; n++)
#pragma unroll
                for (int i = 0; i < 4; i++) c[n][i] = 0.f;

            // S = Q K^T over d=64 (8 k-steps)
#pragma unroll
            for (int k4 = 0; k4 < 8; k4++) {
                int kk = k4 * 8;
                float2 aA = *(float2*)&Qs[qr * AS + kk + 2 * tig];
                float2 aB = *(float2*)&Qs[(qr + 8) * AS + kk + 2 * tig];
                uint32_t a0 = __float_as_uint(aA.x), a1 = __float_as_uint(aB.x);
                uint32_t a2 = __float_as_uint(aA.y), a3 = __float_as_uint(aB.y);
#pragma unroll
                for (int n = 0; n < 8; n++) {
                    float2 b = *(float2*)&Ks[(n * 8 + g) * AS + kk + 2 * tig];
                    mma_tf32(c[n], a0, a1, a2, a3, __float_as_uint(b.x), __float_as_uint(b.y));
                }
            }

            // P = exp(S/8) (tf32-masked), l accumulate, repack, O += P V
#pragma unroll
            for (int n = 0; n < 8; n++) {
                float p0 = tf32_mask(__expf(c[n][0] * 0.125f));
                float p1 = tf32_mask(__expf(c[n][1] * 0.125f));
                float p2 = tf32_mask(__expf(c[n][2] * 0.125f));
                float p3 = tf32_mask(__expf(c[n][3] * 0.125f));
                lacc[m][0] += p0 + p1;
                lacc[m][1] += p2 + p3;

                unsigned srcA = (lane & ~3u) | ((unsigned)tig >> 1);
                int par = tig & 1;
                float x0 = __shfl_sync(0xffffffffu, p0, srcA);
                float x1 = __shfl_sync(0xffffffffu, p1, srcA);
                float x2 = __shfl_sync(0xffffffffu, p0, srcA + 2);
                float x3 = __shfl_sync(0xffffffffu, p1, srcA + 2);
                float y0 = __shfl_sync(0xffffffffu, p2, srcA);
                float y1 = __shfl_sync(0xffffffffu, p3, srcA);
                float y2 = __shfl_sync(0xffffffffu, p2, srcA + 2);
                float y3 = __shfl_sync(0xffffffffu, p3, srcA + 2);
                uint32_t a0 = __float_as_uint(par ? x1 : x0);
                uint32_t a1 = __float_as_uint(par ? y1 : y0);
                uint32_t a2 = __float_as_uint(par ? x3 : x2);
                uint32_t a3 = __float_as_uint(par ? y3 : y2);

#pragma unroll
                for (int dn = 0; dn < 8; dn++) {
                    float2 b = *(float2*)&VTs[(dn * 8 + g) * AS + n * 8 + 2 * tig];
                    mma_tf32(O[m][dn], a0, a1, a2, a3,
                             __float_as_uint(b.x), __float_as_uint(b.y));
                }
            }
        }
        __syncthreads();
    }

    // reduce l across the 4 lanes of each row-group, normalize, store
#pragma unroll
    for (int m = 0; m < 2; m++)
#pragma unroll
        for (int half = 0; half < 2; half++) {
            float l = lacc[m][half];
            l += __shfl_xor_sync(0xffffffffu, l, 1);
            l += __shfl_xor_sync(0xffffffffu, l, 2);
            lacc[m][half] = 1.f / l;
        }

#pragma unroll
    for (int m = 0; m < 2; m++) {
        int r0 = q0 + wid * 32 + m * 16 + g;
#pragma unroll
        for (int dn = 0; dn < 8; dn++) {
            int col = h * 64 + dn * 8 + 2 * tig;
            float2 v0 = make_float2(O[m][dn][0] * lacc[m][0], O[m][dn][1] * lacc[m][0]);
            float2 v1 = make_float2(O[m][dn][2] * lacc[m][1], O[m][dn][3] * lacc[m][1]);
            *(float2*)(ctx + (size_t)r0 * 256 + col) = v0;
            *(float2*)(ctx + (size_t)(r0 + 8) * 256 + col) = v1;
        }
    }
}

// ---------------- launch ----------------
extern "C" void kernel_launch(void* const* d_in, const int* in_sizes, int n_in,
                              void* d_out, int out_size)
{
    (void)in_sizes; (void)n_in; (void)out_size;
    const float* x_term    = (const float*)d_in[0];
    const float* x_symbol  = (const float*)d_in[1];
    const float* x_var     = (const float*)d_in[2];
    const int*   ha_src    = (const int*)d_in[3];
    const int*   ha_dst    = (const int*)d_in[4];
    const int*   so_src    = (const int*)d_in[5];
    const int*   so_dst    = (const int*)d_in[6];
    const int*   vo_src    = (const int*)d_in[7];
    const int*   vo_dst    = (const int*)d_in[8];
    const float* Wl_rha    = (const float*)d_in[9];
    const float* bl_rha    = (const float*)d_in[10];
    const float* Wr_rha    = (const float*)d_in[11];
    const float* Wl_ha     = (const float*)d_in[12];
    const float* bl_ha     = (const float*)d_in[13];
    const float* Wr_ha     = (const float*)d_in[14];
    const float* Wl_rsym   = (const float*)d_in[15];
    const float* bl_rsym   = (const float*)d_in[16];
    const float* Wr_rsym   = (const float*)d_in[17];
    const float* Wl_var    = (const float*)d_in[18];
    const float* bl_var    = (const float*)d_in[19];
    const float* Wr_var    = (const float*)d_in[20];
    const float* ln_g      = (const float*)d_in[21];
    const float* ln_b      = (const float*)d_in[22];
    const float* in_proj_w = (const float*)d_in[23];
    const float* in_proj_b = (const float*)d_in[24];
    const float* out_proj_w= (const float*)d_in[25];
    const float* out_proj_b= (const float*)d_in[26];
    const float* post_w    = (const float*)d_in[27];
    const float* post_b    = (const float*)d_in[28];
    float* out = (float*)d_out;

    cudaFuncSetAttribute(attn_tc_kernel, cudaFuncAttributeMaxDynamicSharedMemorySize, ATTN_SMEM_BYTES);

    float *pAbig, *pWbig, *pbsum, *ppre, *ptout, *pqkv, *pctx, *pattn;
    cudaGetSymbolAddress((void**)&pAbig, g_Abig);
    cudaGetSymbolAddress((void**)&pWbig, g_Wbig);
    cudaGetSymbolAddress((void**)&pbsum, g_bsum);
    cudaGetSymbolAddress((void**)&ppre,  g_pre);
    cudaGetSymbolAddress((void**)&ptout, g_tout);
    cudaGetSymbolAddress((void**)&pqkv,  g_qkv);
    cudaGetSymbolAddress((void**)&pctx,  g_ctx);
    cudaGetSymbolAddress((void**)&pattn, g_attn);

    prep_w_kernel<<<(H * KBIG + 255) / 256, 256>>>(Wl_rha, Wl_ha, Wl_rsym, Wl_var,
                                                   Wr_rha, Wr_ha, Wr_rsym, Wr_var,
                                                   bl_rha, bl_ha, bl_rsym, bl_var);
    init_A_kernel<<<(NT * (KBIG / 4) + 255) / 256, 256>>>(x_term);
    count_kernel<<<(ETOT + 255) / 256, 256>>>(ha_src, ha_dst, so_src, so_dst, vo_src, vo_dst);
    scatter_kernel<<<(ETOT * 64 + 255) / 256, 256>>>(x_term, x_symbol, x_var,
                                                     ha_src, ha_dst, so_src, so_dst, vo_src, vo_dst);
    scale_kernel<<<(NT * 256 + 255) / 256, 256>>>();

    // conv = A_big @ Wbig^T + bsum + x_term  -> g_pre
    gemm_tc_kernel<<<dim3(H / 64, NT / 128), 128>>>(pAbig, pWbig, pbsum, x_term, ppre,
                                                    NT, H, KBIG, 1);
    ln_kernel<<<NT / 8, 256>>>(ppre, ln_g, ln_b, ptout);
    // qkv
    gemm_tc_kernel<<<dim3(3 * H / 64, NT / 128), 128>>>(ptout, in_proj_w, in_proj_b, nullptr, pqkv,
                                                        NT, 3 * H, H, 0);
    // attention
    attn_tc_kernel<<<dim3(NT / 128, NH), 128, ATTN_SMEM_BYTES>>>(pqkv, pctx);
    // out_proj
    gemm_tc_kernel<<<dim3(H / 64, NT / 128), 128>>>(pctx, out_proj_w, out_proj_b, nullptr, pattn,
                                                    NT, H, H, 0);
    // post: relu(attn @ post_w^T + post_b) + term_out -> d_out
    gemm_tc_kernel<<<dim3(H / 64, NT / 128), 128>>>(pattn, post_w, post_b, ptout, out,
                                                    NT, H, H, 2);
}

// round 8
// speedup vs baseline: 2.4769x; 1.6818x over previous
#include <cuda_runtime.h>
#include <math.h>
#include <cstdint>

#define NT 4096
#define NS 2048
#define NV 1024
#define H 256
#define NH 4
#define DH 64
#define E1 65536
#define E2 16384
#define E3 32768
#define ETOT (2*E1 + E2 + E3)
#define KBIG 1280   // [agg0|agg1|agg2|agg3|x_term] blocks of 256

// ---------------- scratch (static device globals; no allocation) ----------------
__device__ float g_Abig[NT * KBIG];
__device__ float g_cnt[4 * NT];
__device__ float g_Wbig[H * KBIG];
__device__ float g_bsum[H];
__device__ float g_pre[NT * H];
__device__ float g_tout[NT * H];
__device__ float g_qkv[NT * 3 * H];
__device__ float g_ctx[NT * H];
__device__ float g_attn[NT * H];

// ---------------- mma.sync tf32 helper ----------------
__device__ __forceinline__ void mma_tf32(float* c, uint32_t a0, uint32_t a1, uint32_t a2, uint32_t a3,
                                         uint32_t b0, uint32_t b1)
{
    asm volatile("mma.sync.aligned.m16n8k8.row.col.f32.tf32.tf32.f32 "
                 "{%0,%1,%2,%3},{%4,%5,%6,%7},{%8,%9},{%0,%1,%2,%3};"
                 : "+f"(c[0]), "+f"(c[1]), "+f"(c[2]), "+f"(c[3])
                 : "r"(a0), "r"(a1), "r"(a2), "r"(a3), "r"(b0), "r"(b1));
}
// interleaved store of one 8-col group: positions (c0,c4,c1,c5)(c2,c6,c3,c7)
// => fragment cols (tig, tig+4) become an adjacent float2 at offset 2*tig.
__device__ __forceinline__ void sts_perm8(float* dst, float4 A0, float4 A1)
{
    *(float4*)dst       = make_float4(A0.x, A1.x, A0.y, A1.y);
    *(float4*)(dst + 4) = make_float4(A0.z, A1.z, A0.w, A1.w);
}
__device__ __forceinline__ float tf32_mask(float x) {
    return __uint_as_float(__float_as_uint(x) & 0xffffe000u);
}

// ---------------- weight prep ----------------
__global__ void prep_w_kernel(const float* __restrict__ Wl0, const float* __restrict__ Wl1,
                              const float* __restrict__ Wl2, const float* __restrict__ Wl3,
                              const float* __restrict__ Wr0, const float* __restrict__ Wr1,
                              const float* __restrict__ Wr2, const float* __restrict__ Wr3,
                              const float* __restrict__ bl0, const float* __restrict__ bl1,
                              const float* __restrict__ bl2, const float* __restrict__ bl3)
{
    int idx = blockIdx.x * blockDim.x + threadIdx.x;
    if (idx < H * KBIG) {
        int h = idx / KBIG, c = idx % KBIG;
        int r = c >> 8, k = c & 255;
        int wi = h * H + k;
        float v;
        if (r == 0)      v = Wl0[wi];
        else if (r == 1) v = Wl1[wi];
        else if (r == 2) v = Wl2[wi];
        else if (r == 3) v = Wl3[wi];
        else             v = Wr0[wi] + Wr1[wi] + Wr2[wi] + Wr3[wi];
        g_Wbig[idx] = v;
    }
    if (idx < H) g_bsum[idx] = bl0[idx] + bl1[idx] + bl2[idx] + bl3[idx];
}

__global__ void init_A_kernel(const float* __restrict__ xt)
{
    int idx = blockIdx.x * blockDim.x + threadIdx.x;
    if (idx < NT * (KBIG / 4)) {
        int n = idx / (KBIG / 4), c4 = idx % (KBIG / 4);
        float4 v;
        if (c4 < 256) v = make_float4(0.f, 0.f, 0.f, 0.f);
        else          v = *((const float4*)(xt + (size_t)n * H) + (c4 - 256));
        ((float4*)g_Abig)[idx] = v;
    }
    if (idx < 4 * NT) g_cnt[idx] = 0.f;
}

__global__ void count_kernel(const int* __restrict__ ha_src, const int* __restrict__ ha_dst,
                             const int* __restrict__ so_src, const int* __restrict__ so_dst,
                             const int* __restrict__ vo_src, const int* __restrict__ vo_dst)
{
    int e = blockIdx.x * blockDim.x + threadIdx.x;
    if (e >= ETOT) return;
    int r, d;
    if (e < E1)               { r = 0; d = ha_src[e]; }
    else if (e < 2 * E1)      { r = 1; d = ha_dst[e - E1]; }
    else if (e < 2 * E1 + E2) { r = 2; d = so_src[e - 2 * E1]; }
    else                      { r = 3; d = vo_dst[e - 2 * E1 - E2]; }
    atomicAdd(&g_cnt[r * NT + d], 1.f);
}

__global__ void scatter_kernel(const float* __restrict__ xt, const float* __restrict__ xs,
                               const float* __restrict__ xv,
                               const int* __restrict__ ha_src, const int* __restrict__ ha_dst,
                               const int* __restrict__ so_src, const int* __restrict__ so_dst,
                               const int* __restrict__ vo_src, const int* __restrict__ vo_dst)
{
    int idx = blockIdx.x * blockDim.x + threadIdx.x;
    if (idx >= ETOT * 64) return;
    int e = idx >> 6, j = idx & 63;
    int r, s, d; const float* x;
    if (e < E1)               { r = 0; s = ha_dst[e];            d = ha_src[e];            x = xt; }
    else if (e < 2 * E1)      { int q = e - E1;          r = 1; s = ha_src[q]; d = ha_dst[q]; x = xt; }
    else if (e < 2 * E1 + E2) { int q = e - 2 * E1;      r = 2; s = so_dst[q]; d = so_src[q]; x = xs; }
    else                      { int q = e - 2 * E1 - E2; r = 3; s = vo_src[q]; d = vo_dst[q]; x = xv; }
    float4 v = *((const float4*)(x + (size_t)s * H) + j);
    float* p = g_Abig + (size_t)d * KBIG + r * H + j * 4;
    asm volatile("red.global.add.v4.f32 [%0], {%1,%2,%3,%4};"
                 :: "l"(p), "f"(v.x), "f"(v.y), "f"(v.z), "f"(v.w) : "memory");
}

__global__ void scale_kernel()
{
    int idx = blockIdx.x * blockDim.x + threadIdx.x;
    if (idx >= NT * 256) return;
    int n = idx >> 8, c4 = idx & 255;
    int r = c4 >> 6;
    float inv = 1.f / fmaxf(g_cnt[r * NT + n], 1.f);
    float4* p = (float4*)(g_Abig + (size_t)n * KBIG) + c4;
    float4 v = *p;
    v.x *= inv; v.y *= inv; v.z *= inv; v.w *= inv;
    *p = v;
}

// ================= tf32 tensor-core GEMM =================
// C[M,N] = A[M,K] @ W[N,K]^T + bias (+epilogue). M%128==0, N%64==0, K%32==0.
// CTA: 256 threads (8 warps), tile 128x64. Warp w: rows 16w..16w+15.
// k-chunk 32, register-prefetch pipeline. Permuted k-columns in smem.
#define GS 40
__global__ __launch_bounds__(256, 1)
void gemm_tc_kernel(const float* __restrict__ A, const float* __restrict__ W,
                    const float* __restrict__ bias, const float* __restrict__ resid,
                    float* __restrict__ C, int M, int N, int K, int mode)
{
    __shared__ __align__(16) float As[128 * GS];
    __shared__ __align__(16) float Ws[64 * GS];
    int tid = threadIdx.x;
    int lane = tid & 31, wid = tid >> 5;
    int g = lane >> 2, tig = lane & 3;
    int rb = blockIdx.y * 128;
    int cb = blockIdx.x * 64;

    int aRow = tid >> 1;            // A: 2 threads per row, 16 cols each
    int aHalf = (tid & 1) * 16;
    int wRow = tid >> 2;            // W: 4 threads per row, 8 cols each
    int wQ = (tid & 3) * 8;

    float4 aR[4], wR[2];
    const float* Ap = A + (size_t)(rb + aRow) * K + aHalf;
    const float* Wp = W + (size_t)(cb + wRow) * K + wQ;

#pragma unroll
    for (int j = 0; j < 4; j++) aR[j] = *(const float4*)(Ap + j * 4);
#pragma unroll
    for (int j = 0; j < 2; j++) wR[j] = *(const float4*)(Wp + j * 4);

    float acc[8][4];
#pragma unroll
    for (int n = 0; n < 8; n++)
#pragma unroll
        for (int i = 0; i < 4; i++) acc[n][i] = 0.f;

    int nchunk = K >> 5;
    for (int kc = 0; kc < nchunk; kc++) {
#pragma unroll
        for (int j2 = 0; j2 < 2; j2++)
            sts_perm8(As + aRow * GS + aHalf + j2 * 8, aR[2 * j2], aR[2 * j2 + 1]);
        sts_perm8(Ws + wRow * GS + wQ, wR[0], wR[1]);
        __syncthreads();

        if (kc + 1 < nchunk) {
            const float* Ap2 = Ap + (kc + 1) * 32;
            const float* Wp2 = Wp + (kc + 1) * 32;
#pragma unroll
            for (int j = 0; j < 4; j++) aR[j] = *(const float4*)(Ap2 + j * 4);
#pragma unroll
            for (int j = 0; j < 2; j++) wR[j] = *(const float4*)(Wp2 + j * 4);
        }

        int r0 = wid * 16 + g;
#pragma unroll
        for (int k4 = 0; k4 < 4; k4++) {
            int kk = k4 * 8;
            float2 aA = *(float2*)&As[r0 * GS + kk + 2 * tig];
            float2 aB = *(float2*)&As[(r0 + 8) * GS + kk + 2 * tig];
            uint32_t a0 = __float_as_uint(aA.x), a1 = __float_as_uint(aB.x);
            uint32_t a2 = __float_as_uint(aA.y), a3 = __float_as_uint(aB.y);
#pragma unroll
            for (int n = 0; n < 8; n++) {
                float2 b = *(float2*)&Ws[(n * 8 + g) * GS + kk + 2 * tig];
                mma_tf32(acc[n], a0, a1, a2, a3, __float_as_uint(b.x), __float_as_uint(b.y));
            }
        }
        __syncthreads();
    }

    // epilogue
    int r0 = rb + wid * 16 + g;
#pragma unroll
    for (int n = 0; n < 8; n++) {
        int col = cb + n * 8 + 2 * tig;
        float2 bv = *(const float2*)(bias + col);
        float2 v0 = make_float2(acc[n][0] + bv.x, acc[n][1] + bv.y);
        float2 v1 = make_float2(acc[n][2] + bv.x, acc[n][3] + bv.y);
        if (mode == 2) {
            v0.x = fmaxf(v0.x, 0.f); v0.y = fmaxf(v0.y, 0.f);
            v1.x = fmaxf(v1.x, 0.f); v1.y = fmaxf(v1.y, 0.f);
        }
        if (mode >= 1) {
            float2 r0v = *(const float2*)(resid + (size_t)r0 * N + col);
            float2 r1v = *(const float2*)(resid + (size_t)(r0 + 8) * N + col);
            v0.x += r0v.x; v0.y += r0v.y; v1.x += r1v.x; v1.y += r1v.y;
        }
        *(float2*)(C + (size_t)r0 * N + col) = v0;
        *(float2*)(C + (size_t)(r0 + 8) * N + col) = v1;
    }
}

// ---------------- layernorm ----------------
__global__ __launch_bounds__(256)
void ln_kernel(const float* __restrict__ pre, const float* __restrict__ gam,
               const float* __restrict__ bet, float* __restrict__ out)
{
    int row = blockIdx.x * 8 + (threadIdx.x >> 5);
    int lane = threadIdx.x & 31;
    const float* p = pre + (size_t)row * H + lane * 8;
    float4 a = *(const float4*)p;
    float4 b = *(const float4*)(p + 4);
    float s = a.x + a.y + a.z + a.w + b.x + b.y + b.z + b.w;
#pragma unroll
    for (int off = 16; off; off >>= 1) s += __shfl_xor_sync(0xffffffffu, s, off);
    float mu = s * (1.f / H);
    float dx[8] = {a.x - mu, a.y - mu, a.z - mu, a.w - mu, b.x - mu, b.y - mu, b.z - mu, b.w - mu};
    float vs = 0.f;
#pragma unroll
    for (int i = 0; i < 8; i++) vs += dx[i] * dx[i];
#pragma unroll
    for (int off = 16; off; off >>= 1) vs += __shfl_xor_sync(0xffffffffu, vs, off);
    float rstd = rsqrtf(vs * (1.f / H) + 1e-5f);
    float4 g0 = *(const float4*)(gam + lane * 8);
    float4 g1 = *(const float4*)(gam + lane * 8 + 4);
    float4 b0 = *(const float4*)(bet + lane * 8);
    float4 b1 = *(const float4*)(bet + lane * 8 + 4);
    float4 o0 = make_float4(dx[0] * rstd * g0.x + b0.x, dx[1] * rstd * g0.y + b0.y,
                            dx[2] * rstd * g0.z + b0.z, dx[3] * rstd * g0.w + b0.w);
    float4 o1 = make_float4(dx[4] * rstd * g1.x + b1.x, dx[5] * rstd * g1.y + b1.y,
                            dx[6] * rstd * g1.z + b1.z, dx[7] * rstd * g1.w + b1.w);
    float* q = out + (size_t)row * H + lane * 8;
    *(float4*)q = o0;
    *(float4*)(q + 4) = o1;
}

// ================= tf32 mma.sync flash attention =================
// CTA: 256 threads (8 warps), 128 q-rows, one head. Key tiles of 64.
// Warp w owns q rows 16w..16w+15. Fixed-shift softmax (scores bounded).
// smem: Qs[128][72], Ks[64][72] (permuted d-cols), VTs[64][72] (V^T, permuted key-cols).
#define AS 72
#define ATTN_SMEM_BYTES ((128 + 64 + 64) * AS * 4)

__global__ __launch_bounds__(256, 1)
void attn_tc_kernel(const float* __restrict__ qkv, float* __restrict__ ctx)
{
    extern __shared__ __align__(16) float sm[];
    float* Qs  = sm;
    float* Ks  = sm + 128 * AS;
    float* VTs = Ks + 64 * AS;

    int tid = threadIdx.x;
    int lane = tid & 31, wid = tid >> 5;
    int g = lane >> 2, tig = lane & 3;
    int h = blockIdx.y;
    int q0 = blockIdx.x * 128;

    // ---- load Q (once), permuted d-columns; 2 threads per row ----
    {
        int qRow = tid >> 1, qHalf = (tid & 1) * 32;
        const float* qr = qkv + (size_t)(q0 + qRow) * 768 + h * 64 + qHalf;
#pragma unroll
        for (int j2 = 0; j2 < 4; j2++) {
            float4 A0 = *(const float4*)(qr + j2 * 8);
            float4 A1 = *(const float4*)(qr + j2 * 8 + 4);
            sts_perm8(Qs + qRow * AS + qHalf + j2 * 8, A0, A1);
        }
    }

    // K/V prefetch: 4 threads per K row, 16 cols each.
    int kRow = tid >> 2;
    int kQ = (tid & 3) * 16;
    int vpos = (kRow & ~7) | (2 * (kRow & 3)) | ((kRow >> 2) & 1);  // permuted key position
    float4 Kbuf[4], Vbuf[4];
    {
        const float* kp = qkv + (size_t)kRow * 768 + 256 + h * 64 + kQ;
#pragma unroll
        for (int j = 0; j < 4; j++) Kbuf[j] = *(const float4*)(kp + j * 4);
#pragma unroll
        for (int j = 0; j < 4; j++) Vbuf[j] = *(const float4*)(kp + 256 + j * 4);
    }

    float O[8][4];
#pragma unroll
    for (int n = 0; n < 8; n++)
#pragma unroll
        for (int i = 0; i < 4; i++) O[n][i] = 0.f;
    float lacc[2] = {0.f, 0.f};

    for (int kt = 0; kt < 64; kt++) {
        // store prefetched K (permuted d-cols) and V^T (permuted key-cols)
#pragma unroll
        for (int j2 = 0; j2 < 2; j2++)
            sts_perm8(Ks + kRow * AS + kQ + j2 * 8, Kbuf[2 * j2], Kbuf[2 * j2 + 1]);
#pragma unroll
        for (int j = 0; j < 4; j++) {
            int d = kQ + j * 4;
            VTs[(d + 0) * AS + vpos] = Vbuf[j].x;
            VTs[(d + 1) * AS + vpos] = Vbuf[j].y;
            VTs[(d + 2) * AS + vpos] = Vbuf[j].z;
            VTs[(d + 3) * AS + vpos] = Vbuf[j].w;
        }
        __syncthreads();

        if (kt + 1 < 64) {
            const float* kp = qkv + (size_t)((kt + 1) * 64 + kRow) * 768 + 256 + h * 64 + kQ;
#pragma unroll
            for (int j = 0; j < 4; j++) Kbuf[j] = *(const float4*)(kp + j * 4);
#pragma unroll
            for (int j = 0; j < 4; j++) Vbuf[j] = *(const float4*)(kp + 256 + j * 4);
        }

        int qr = wid * 16 + g;
        float c[8][4];
#pragma unroll
        for (int n = 0; n < 8; n++)
#pragma unroll
            for (int i = 0; i < 4; i++) c[n][i] = 0.f;

        // S = Q K^T over d=64 (8 k-steps)
#pragma unroll
        for (int k4 = 0; k4 < 8; k4++) {
            int kk = k4 * 8;
            float2 aA = *(float2*)&Qs[qr * AS + kk + 2 * tig];
            float2 aB = *(float2*)&Qs[(qr + 8) * AS + kk + 2 * tig];
            uint32_t a0 = __float_as_uint(aA.x), a1 = __float_as_uint(aB.x);
            uint32_t a2 = __float_as_uint(aA.y), a3 = __float_as_uint(aB.y);
#pragma unroll
            for (int n = 0; n < 8; n++) {
                float2 b = *(float2*)&Ks[(n * 8 + g) * AS + kk + 2 * tig];
                mma_tf32(c[n], a0, a1, a2, a3, __float_as_uint(b.x), __float_as_uint(b.y));
            }
        }

        // P = exp(S/8) (tf32-masked), l accumulate, repack, O += P V
#pragma unroll
        for (int n = 0; n < 8; n++) {
            float p0 = tf32_mask(__expf(c[n][0] * 0.125f));
            float p1 = tf32_mask(__expf(c[n][1] * 0.125f));
            float p2 = tf32_mask(__expf(c[n][2] * 0.125f));
            float p3 = tf32_mask(__expf(c[n][3] * 0.125f));
            lacc[0] += p0 + p1;
            lacc[1] += p2 + p3;

            unsigned srcA = (lane & ~3u) | ((unsigned)tig >> 1);
            int par = tig & 1;
            float x0 = __shfl_sync(0xffffffffu, p0, srcA);
            float x1 = __shfl_sync(0xffffffffu, p1, srcA);
            float x2 = __shfl_sync(0xffffffffu, p0, srcA + 2);
            float x3 = __shfl_sync(0xffffffffu, p1, srcA + 2);
            float y0 = __shfl_sync(0xffffffffu, p2, srcA);
            float y1 = __shfl_sync(0xffffffffu, p3, srcA);
            float y2 = __shfl_sync(0xffffffffu, p2, srcA + 2);
            float y3 = __shfl_sync(0xffffffffu, p3, srcA + 2);
            uint32_t a0 = __float_as_uint(par ? x1 : x0);
            uint32_t a1 = __float_as_uint(par ? y1 : y0);
            uint32_t a2 = __float_as_uint(par ? x3 : x2);
            uint32_t a3 = __float_as_uint(par ? y3 : y2);

#pragma unroll
            for (int dn = 0; dn < 8; dn++) {
                float2 b = *(float2*)&VTs[(dn * 8 + g) * AS + n * 8 + 2 * tig];
                mma_tf32(O[dn], a0, a1, a2, a3,
                         __float_as_uint(b.x), __float_as_uint(b.y));
            }
        }
        __syncthreads();
    }

    // reduce l across the 4 lanes of each row-group, normalize, store
#pragma unroll
    for (int half = 0; half < 2; half++) {
        float l = lacc[half];
        l += __shfl_xor_sync(0xffffffffu, l, 1);
        l += __shfl_xor_sync(0xffffffffu, l, 2);
        lacc[half] = 1.f / l;
    }

    int r0 = q0 + wid * 16 + g;
#pragma unroll
    for (int dn = 0; dn < 8; dn++) {
        int col = h * 64 + dn * 8 + 2 * tig;
        float2 v0 = make_float2(O[dn][0] * lacc[0], O[dn][1] * lacc[0]);
        float2 v1 = make_float2(O[dn][2] * lacc[1], O[dn][3] * lacc[1]);
        *(float2*)(ctx + (size_t)r0 * 256 + col) = v0;
        *(float2*)(ctx + (size_t)(r0 + 8) * 256 + col) = v1;
    }
}

// ---------------- launch ----------------
extern "C" void kernel_launch(void* const* d_in, const int* in_sizes, int n_in,
                              void* d_out, int out_size)
{
    (void)in_sizes; (void)n_in; (void)out_size;
    const float* x_term    = (const float*)d_in[0];
    const float* x_symbol  = (const float*)d_in[1];
    const float* x_var     = (const float*)d_in[2];
    const int*   ha_src    = (const int*)d_in[3];
    const int*   ha_dst    = (const int*)d_in[4];
    const int*   so_src    = (const int*)d_in[5];
    const int*   so_dst    = (const int*)d_in[6];
    const int*   vo_src    = (const int*)d_in[7];
    const int*   vo_dst    = (const int*)d_in[8];
    const float* Wl_rha    = (const float*)d_in[9];
    const float* bl_rha    = (const float*)d_in[10];
    const float* Wr_rha    = (const float*)d_in[11];
    const float* Wl_ha     = (const float*)d_in[12];
    const float* bl_ha     = (const float*)d_in[13];
    const float* Wr_ha     = (const float*)d_in[14];
    const float* Wl_rsym   = (const float*)d_in[15];
    const float* bl_rsym   = (const float*)d_in[16];
    const float* Wr_rsym   = (const float*)d_in[17];
    const float* Wl_var    = (const float*)d_in[18];
    const float* bl_var    = (const float*)d_in[19];
    const float* Wr_var    = (const float*)d_in[20];
    const float* ln_g      = (const float*)d_in[21];
    const float* ln_b      = (const float*)d_in[22];
    const float* in_proj_w = (const float*)d_in[23];
    const float* in_proj_b = (const float*)d_in[24];
    const float* out_proj_w= (const float*)d_in[25];
    const float* out_proj_b= (const float*)d_in[26];
    const float* post_w    = (const float*)d_in[27];
    const float* post_b    = (const float*)d_in[28];
    float* out = (float*)d_out;

    cudaFuncSetAttribute(attn_tc_kernel, cudaFuncAttributeMaxDynamicSharedMemorySize, ATTN_SMEM_BYTES);

    float *pAbig, *pWbig, *pbsum, *ppre, *ptout, *pqkv, *pctx, *pattn;
    cudaGetSymbolAddress((void**)&pAbig, g_Abig);
    cudaGetSymbolAddress((void**)&pWbig, g_Wbig);
    cudaGetSymbolAddress((void**)&pbsum, g_bsum);
    cudaGetSymbolAddress((void**)&ppre,  g_pre);
    cudaGetSymbolAddress((void**)&ptout, g_tout);
    cudaGetSymbolAddress((void**)&pqkv,  g_qkv);
    cudaGetSymbolAddress((void**)&pctx,  g_ctx);
    cudaGetSymbolAddress((void**)&pattn, g_attn);

    prep_w_kernel<<<(H * KBIG + 255) / 256, 256>>>(Wl_rha, Wl_ha, Wl_rsym, Wl_var,
                                                   Wr_rha, Wr_ha, Wr_rsym, Wr_var,
                                                   bl_rha, bl_ha, bl_rsym, bl_var);
    init_A_kernel<<<(NT * (KBIG / 4) + 255) / 256, 256>>>(x_term);
    count_kernel<<<(ETOT + 255) / 256, 256>>>(ha_src, ha_dst, so_src, so_dst, vo_src, vo_dst);
    scatter_kernel<<<(ETOT * 64 + 255) / 256, 256>>>(x_term, x_symbol, x_var,
                                                     ha_src, ha_dst, so_src, so_dst, vo_src, vo_dst);
    scale_kernel<<<(NT * 256 + 255) / 256, 256>>>();

    // conv = A_big @ Wbig^T + bsum + x_term  -> g_pre
    gemm_tc_kernel<<<dim3(H / 64, NT / 128), 256>>>(pAbig, pWbig, pbsum, x_term, ppre,
                                                    NT, H, KBIG, 1);
    ln_kernel<<<NT / 8, 256>>>(ppre, ln_g, ln_b, ptout);
    // qkv
    gemm_tc_kernel<<<dim3(3 * H / 64, NT / 128), 256>>>(ptout, in_proj_w, in_proj_b, nullptr, pqkv,
                                                        NT, 3 * H, H, 0);
    // attention
    attn_tc_kernel<<<dim3(NT / 128, NH), 256, ATTN_SMEM_BYTES>>>(pqkv, pctx);
    // out_proj
    gemm_tc_kernel<<<dim3(H / 64, NT / 128), 256>>>(pctx, out_proj_w, out_proj_b, nullptr, pattn,
                                                    NT, H, H, 0);
    // post: relu(attn @ post_w^T + post_b) + term_out -> d_out
    gemm_tc_kernel<<<dim3(H / 64, NT / 128), 256>>>(pattn, post_w, post_b, ptout, out,
                                                    NT, H, H, 2);
}

// round 10
// speedup vs baseline: 2.5269x; 1.0202x over previous
#include <cuda_runtime.h>
#include <math.h>
#include <cstdint>

#define NT 4096
#define NS 2048
#define NV 1024
#define H 256
#define NH 4
#define DH 64
#define E1 65536
#define E2 16384
#define E3 32768
#define ETOT (2*E1 + E2 + E3)
#define KBIG 1280   // [agg0|agg1|agg2|agg3|x_term] blocks of 256

// ---------------- scratch (static device globals; no allocation) ----------------
__device__ float g_Abig[NT * KBIG];
__device__ float g_cnt[4 * NT];
__device__ float g_Wbig[H * KBIG];
__device__ float g_bsum[H];
__device__ float g_pre[NT * H];
__device__ float g_tout[NT * H];
__device__ float g_qkv[NT * 3 * H];
__device__ float g_ctx[NT * H];
__device__ float g_attn[NT * H];

// ---------------- mma.sync tf32 helper ----------------
__device__ __forceinline__ void mma_tf32(float* c, uint32_t a0, uint32_t a1, uint32_t a2, uint32_t a3,
                                         uint32_t b0, uint32_t b1)
{
    asm volatile("mma.sync.aligned.m16n8k8.row.col.f32.tf32.tf32.f32 "
                 "{%0,%1,%2,%3},{%4,%5,%6,%7},{%8,%9},{%0,%1,%2,%3};"
                 : "+f"(c[0]), "+f"(c[1]), "+f"(c[2]), "+f"(c[3])
                 : "r"(a0), "r"(a1), "r"(a2), "r"(a3), "r"(b0), "r"(b1));
}
// interleaved store of one 8-col group: positions (c0,c4,c1,c5)(c2,c6,c3,c7)
__device__ __forceinline__ void sts_perm8(float* dst, float4 A0, float4 A1)
{
    *(float4*)dst       = make_float4(A0.x, A1.x, A0.y, A1.y);
    *(float4*)(dst + 4) = make_float4(A0.z, A1.z, A0.w, A1.w);
}
__device__ __forceinline__ float tf32_mask(float x) {
    return __uint_as_float(__float_as_uint(x) & 0xffffe000u);
}
__device__ __forceinline__ float4 scale4(float4 v, float s) {
    return make_float4(v.x * s, v.y * s, v.z * s, v.w * s);
}

// ---------------- fused prep: Wbig/bsum + A_big init + cnt zero ----------------
__global__ void prep_init_kernel(const float* __restrict__ xt,
                                 const float* __restrict__ Wl0, const float* __restrict__ Wl1,
                                 const float* __restrict__ Wl2, const float* __restrict__ Wl3,
                                 const float* __restrict__ Wr0, const float* __restrict__ Wr1,
                                 const float* __restrict__ Wr2, const float* __restrict__ Wr3,
                                 const float* __restrict__ bl0, const float* __restrict__ bl1,
                                 const float* __restrict__ bl2, const float* __restrict__ bl3)
{
    int idx = blockIdx.x * blockDim.x + threadIdx.x;
    if (idx < NT * (KBIG / 4)) {
        int n = idx / (KBIG / 4), c4 = idx % (KBIG / 4);
        float4 v;
        if (c4 < 256) v = make_float4(0.f, 0.f, 0.f, 0.f);
        else          v = *((const float4*)(xt + (size_t)n * H) + (c4 - 256));
        ((float4*)g_Abig)[idx] = v;
    }
    if (idx < H * KBIG) {
        int h = idx / KBIG, c = idx % KBIG;
        int r = c >> 8, k = c & 255;
        int wi = h * H + k;
        float v;
        if (r == 0)      v = Wl0[wi];
        else if (r == 1) v = Wl1[wi];
        else if (r == 2) v = Wl2[wi];
        else if (r == 3) v = Wl3[wi];
        else             v = Wr0[wi] + Wr1[wi] + Wr2[wi] + Wr3[wi];
        g_Wbig[idx] = v;
    }
    if (idx < 4 * NT) g_cnt[idx] = 0.f;
    if (idx < H) g_bsum[idx] = bl0[idx] + bl1[idx] + bl2[idx] + bl3[idx];
}

// ---------------- scatter-add messages + degree counts (32 thr/edge, MLP=2) ----------------
__global__ void scatter_kernel(const float* __restrict__ xt, const float* __restrict__ xs,
                               const float* __restrict__ xv,
                               const int* __restrict__ ha_src, const int* __restrict__ ha_dst,
                               const int* __restrict__ so_src, const int* __restrict__ so_dst,
                               const int* __restrict__ vo_src, const int* __restrict__ vo_dst)
{
    int idx = blockIdx.x * blockDim.x + threadIdx.x;
    if (idx >= ETOT * 32) return;
    int e = idx >> 5, j = idx & 31;
    int r, s, d; const float* x;
    if (e < E1)               { r = 0; s = ha_dst[e];            d = ha_src[e];            x = xt; }
    else if (e < 2 * E1)      { int q = e - E1;          r = 1; s = ha_src[q]; d = ha_dst[q]; x = xt; }
    else if (e < 2 * E1 + E2) { int q = e - 2 * E1;      r = 2; s = so_dst[q]; d = so_src[q]; x = xs; }
    else                      { int q = e - 2 * E1 - E2; r = 3; s = vo_src[q]; d = vo_dst[q]; x = xv; }
    const float4* src = (const float4*)(x + (size_t)s * H);
    float4 v0 = src[j];
    float4 v1 = src[j + 32];
    float* p = g_Abig + (size_t)d * KBIG + r * H + j * 4;
    asm volatile("red.global.add.v4.f32 [%0], {%1,%2,%3,%4};"
                 :: "l"(p), "f"(v0.x), "f"(v0.y), "f"(v0.z), "f"(v0.w) : "memory");
    asm volatile("red.global.add.v4.f32 [%0], {%1,%2,%3,%4};"
                 :: "l"(p + 128), "f"(v1.x), "f"(v1.y), "f"(v1.z), "f"(v1.w) : "memory");
    if (j == 0) atomicAdd(&g_cnt[r * NT + d], 1.f);
}

// ================= tf32 tensor-core GEMM (3-stage smem pipeline) =================
// C[M,N] = A[M,K] @ W[N,K]^T + bias (+epilogue). cnt!=null => conv mode: scale
// agg blocks (chunks 0..31) of A by 1/max(cnt,1) at smem-store time.
#define GS 40
#define GSTG (192 * GS)      // floats per stage: As 128 rows + Ws 64 rows
__global__ __launch_bounds__(256, 1)
void gemm_tc_kernel(const float* __restrict__ A, const float* __restrict__ W,
                    const float* __restrict__ bias, const float* __restrict__ resid,
                    const float* __restrict__ cnt,
                    float* __restrict__ C, int M, int N, int K, int mode)
{
    __shared__ __align__(16) float S[3 * GSTG];
    int tid = threadIdx.x;
    int lane = tid & 31, wid = tid >> 5;
    int g = lane >> 2, tig = lane & 3;
    int rb = blockIdx.y * 128;
    int cb = blockIdx.x * 64;

    int aRow = tid >> 1;            // A: 2 threads per row, 16 cols each
    int aHalf = (tid & 1) * 16;
    int wRow = tid >> 2;            // W: 4 threads per row, 8 cols each
    int wQ = (tid & 3) * 8;

    float inv[4] = {1.f, 1.f, 1.f, 1.f};
    if (cnt) {
#pragma unroll
        for (int r = 0; r < 4; r++)
            inv[r] = 1.f / fmaxf(cnt[r * NT + rb + aRow], 1.f);
    }

    float4 aR[4], wR[2];
    const float* Ap = A + (size_t)(rb + aRow) * K + aHalf;
    const float* Wp = W + (size_t)(cb + wRow) * K + wQ;

    auto loadC = [&](int kc) {
        const float* Ap2 = Ap + kc * 32;
        const float* Wp2 = Wp + kc * 32;
#pragma unroll
        for (int j = 0; j < 4; j++) aR[j] = *(const float4*)(Ap2 + j * 4);
#pragma unroll
        for (int j = 0; j < 2; j++) wR[j] = *(const float4*)(Wp2 + j * 4);
    };
    auto storeC = [&](int kc, int stg) {
        float* As = S + stg * GSTG;
        float* Ws = As + 128 * GS;
        float sc = (cnt && kc < 32) ? inv[kc >> 3] : 1.f;
#pragma unroll
        for (int j2 = 0; j2 < 2; j2++)
            sts_perm8(As + aRow * GS + aHalf + j2 * 8,
                      scale4(aR[2 * j2], sc), scale4(aR[2 * j2 + 1], sc));
        sts_perm8(Ws + wRow * GS + wQ, wR[0], wR[1]);
    };

    float acc[8][4];
#pragma unroll
    for (int n = 0; n < 8; n++)
#pragma unroll
        for (int i = 0; i < 4; i++) acc[n][i] = 0.f;

    int nchunk = K >> 5;
    loadC(0); storeC(0, 0);
    loadC(1); storeC(1, 1);
    __syncthreads();

    int r0 = wid * 16 + g;
    for (int kc = 0; kc < nchunk; kc++) {
        int cur = kc % 3;
        bool pf = (kc + 2) < nchunk;
        if (pf) loadC(kc + 2);

        const float* As = S + cur * GSTG;
        const float* Ws = As + 128 * GS;
#pragma unroll
        for (int k4 = 0; k4 < 4; k4++) {
            int kk = k4 * 8;
            float2 aA = *(float2*)&As[r0 * GS + kk + 2 * tig];
            float2 aB = *(float2*)&As[(r0 + 8) * GS + kk + 2 * tig];
            uint32_t a0 = __float_as_uint(aA.x), a1 = __float_as_uint(aB.x);
            uint32_t a2 = __float_as_uint(aA.y), a3 = __float_as_uint(aB.y);
#pragma unroll
            for (int n = 0; n < 8; n++) {
                float2 b = *(float2*)&Ws[(n * 8 + g) * GS + kk + 2 * tig];
                mma_tf32(acc[n], a0, a1, a2, a3, __float_as_uint(b.x), __float_as_uint(b.y));
            }
        }
        __syncthreads();
        if (pf) storeC(kc + 2, (kc + 2) % 3);
    }

    // epilogue
    int gr0 = rb + wid * 16 + g;
#pragma unroll
    for (int n = 0; n < 8; n++) {
        int col = cb + n * 8 + 2 * tig;
        float2 bv = *(const float2*)(bias + col);
        float2 v0 = make_float2(acc[n][0] + bv.x, acc[n][1] + bv.y);
        float2 v1 = make_float2(acc[n][2] + bv.x, acc[n][3] + bv.y);
        if (mode == 2) {
            v0.x = fmaxf(v0.x, 0.f); v0.y = fmaxf(v0.y, 0.f);
            v1.x = fmaxf(v1.x, 0.f); v1.y = fmaxf(v1.y, 0.f);
        }
        if (mode >= 1) {
            float2 r0v = *(const float2*)(resid + (size_t)gr0 * N + col);
            float2 r1v = *(const float2*)(resid + (size_t)(gr0 + 8) * N + col);
            v0.x += r0v.x; v0.y += r0v.y; v1.x += r1v.x; v1.y += r1v.y;
        }
        *(float2*)(C + (size_t)gr0 * N + col) = v0;
        *(float2*)(C + (size_t)(gr0 + 8) * N + col) = v1;
    }
}

// ---------------- layernorm ----------------
__global__ __launch_bounds__(256)
void ln_kernel(const float* __restrict__ pre, const float* __restrict__ gam,
               const float* __restrict__ bet, float* __restrict__ out)
{
    int row = blockIdx.x * 8 + (threadIdx.x >> 5);
    int lane = threadIdx.x & 31;
    const float* p = pre + (size_t)row * H + lane * 8;
    float4 a = *(const float4*)p;
    float4 b = *(const float4*)(p + 4);
    float s = a.x + a.y + a.z + a.w + b.x + b.y + b.z + b.w;
#pragma unroll
    for (int off = 16; off; off >>= 1) s += __shfl_xor_sync(0xffffffffu, s, off);
    float mu = s * (1.f / H);
    float dx[8] = {a.x - mu, a.y - mu, a.z - mu, a.w - mu, b.x - mu, b.y - mu, b.z - mu, b.w - mu};
    float vs = 0.f;
#pragma unroll
    for (int i = 0; i < 8; i++) vs += dx[i] * dx[i];
#pragma unroll
    for (int off = 16; off; off >>= 1) vs += __shfl_xor_sync(0xffffffffu, vs, off);
    float rstd = rsqrtf(vs * (1.f / H) + 1e-5f);
    float4 g0 = *(const float4*)(gam + lane * 8);
    float4 g1 = *(const float4*)(gam + lane * 8 + 4);
    float4 b0 = *(const float4*)(bet + lane * 8);
    float4 b1 = *(const float4*)(bet + lane * 8 + 4);
    float4 o0 = make_float4(dx[0] * rstd * g0.x + b0.x, dx[1] * rstd * g0.y + b0.y,
                            dx[2] * rstd * g0.z + b0.z, dx[3] * rstd * g0.w + b0.w);
    float4 o1 = make_float4(dx[4] * rstd * g1.x + b1.x, dx[5] * rstd * g1.y + b1.y,
                            dx[6] * rstd * g1.z + b1.z, dx[7] * rstd * g1.w + b1.w);
    float* q = out + (size_t)row * H + lane * 8;
    *(float4*)q = o0;
    *(float4*)(q + 4) = o1;
}

// ================= tf32 mma.sync flash attention (3-stage KV pipeline) =================
// CTA: 256 threads (8 warps), 128 q-rows, one head. Key tiles of 64, one sync/tile.
#define AS 72
#define QFL (128 * AS)
#define KVSTG (128 * AS)    // 64 K rows + 64 VT rows per stage
#define ATTN_SMEM_BYTES ((QFL + 3 * KVSTG) * 4)

__global__ __launch_bounds__(256, 1)
void attn_tc_kernel(const float* __restrict__ qkv, float* __restrict__ ctx)
{
    extern __shared__ __align__(16) float sm[];
    float* Qs = sm;

    int tid = threadIdx.x;
    int lane = tid & 31, wid = tid >> 5;
    int g = lane >> 2, tig = lane & 3;
    int h = blockIdx.y;
    int q0 = blockIdx.x * 128;

    // ---- load Q (once), permuted d-columns; 2 threads per row ----
    {
        int qRow = tid >> 1, qHalf = (tid & 1) * 32;
        const float* qr = qkv + (size_t)(q0 + qRow) * 768 + h * 64 + qHalf;
#pragma unroll
        for (int j2 = 0; j2 < 4; j2++) {
            float4 A0 = *(const float4*)(qr + j2 * 8);
            float4 A1 = *(const float4*)(qr + j2 * 8 + 4);
            sts_perm8(Qs + qRow * AS + qHalf + j2 * 8, A0, A1);
        }
    }

    // K/V: 4 threads per K row, 16 cols each.
    int kRow = tid >> 2;
    int kQ = (tid & 3) * 16;
    int vpos = (kRow & ~7) | (2 * (kRow & 3)) | ((kRow >> 2) & 1);  // permuted key position
    float4 Kbuf[4], Vbuf[4];

    auto loadKV = [&](int kt) {
        const float* kp = qkv + (size_t)(kt * 64 + kRow) * 768 + 256 + h * 64 + kQ;
#pragma unroll
        for (int j = 0; j < 4; j++) Kbuf[j] = *(const float4*)(kp + j * 4);
#pragma unroll
        for (int j = 0; j < 4; j++) Vbuf[j] = *(const float4*)(kp + 256 + j * 4);
    };
    auto storeKV = [&](int stg) {
        float* Ks  = sm + QFL + stg * KVSTG;
        float* VTs = Ks + 64 * AS;
#pragma unroll
        for (int j2 = 0; j2 < 2; j2++)
            sts_perm8(Ks + kRow * AS + kQ + j2 * 8, Kbuf[2 * j2], Kbuf[2 * j2 + 1]);
#pragma unroll
        for (int j = 0; j < 4; j++) {
            int d = kQ + j * 4;
            VTs[(d + 0) * AS + vpos] = Vbuf[j].x;
            VTs[(d + 1) * AS + vpos] = Vbuf[j].y;
            VTs[(d + 2) * AS + vpos] = Vbuf[j].z;
            VTs[(d + 3) * AS + vpos] = Vbuf[j].w;
        }
    };

    float O[8][4];
#pragma unroll
    for (int n = 0; n < 8; n++)
#pragma unroll
        for (int i = 0; i < 4; i++) O[n][i] = 0.f;
    float lacc[2] = {0.f, 0.f};

    loadKV(0); storeKV(0);
    loadKV(1); storeKV(1);
    __syncthreads();

    int qr = wid * 16 + g;
    for (int kt = 0; kt < 64; kt++) {
        int cur = kt % 3;
        bool pf = (kt + 2) < 64;
        if (pf) loadKV(kt + 2);

        const float* Ks  = sm + QFL + cur * KVSTG;
        const float* VTs = Ks + 64 * AS;

        float c[8][4];
#pragma unroll
        for (int n = 0; n < 8; n++)
#pragma unroll
            for (int i = 0; i < 4; i++) c[n][i] = 0.f;

        // S = Q K^T over d=64 (8 k-steps)
#pragma unroll
        for (int k4 = 0; k4 < 8; k4++) {
            int kk = k4 * 8;
            float2 aA = *(float2*)&Qs[qr * AS + kk + 2 * tig];
            float2 aB = *(float2*)&Qs[(qr + 8) * AS + kk + 2 * tig];
            uint32_t a0 = __float_as_uint(aA.x), a1 = __float_as_uint(aB.x);
            uint32_t a2 = __float_as_uint(aA.y), a3 = __float_as_uint(aB.y);
#pragma unroll
            for (int n = 0; n < 8; n++) {
                float2 b = *(float2*)&Ks[(n * 8 + g) * AS + kk + 2 * tig];
                mma_tf32(c[n], a0, a1, a2, a3, __float_as_uint(b.x), __float_as_uint(b.y));
            }
        }

        // P = exp(S/8) (tf32-masked), l accumulate, repack, O += P V
#pragma unroll
        for (int n = 0; n < 8; n++) {
            float p0 = tf32_mask(__expf(c[n][0] * 0.125f));
            float p1 = tf32_mask(__expf(c[n][1] * 0.125f));
            float p2 = tf32_mask(__expf(c[n][2] * 0.125f));
            float p3 = tf32_mask(__expf(c[n][3] * 0.125f));
            lacc[0] += p0 + p1;
            lacc[1] += p2 + p3;

            unsigned srcA = (lane & ~3u) | ((unsigned)tig >> 1);
            int par = tig & 1;
            float x0 = __shfl_sync(0xffffffffu, p0, srcA);
            float x1 = __shfl_sync(0xffffffffu, p1, srcA);
            float x2 = __shfl_sync(0xffffffffu, p0, srcA + 2);
            float x3 = __shfl_sync(0xffffffffu, p1, srcA + 2);
            float y0 = __shfl_sync(0xffffffffu, p2, srcA);
            float y1 = __shfl_sync(0xffffffffu, p3, srcA);
            float y2 = __shfl_sync(0xffffffffu, p2, srcA + 2);
            float y3 = __shfl_sync(0xffffffffu, p3, srcA + 2);
            uint32_t a0 = __float_as_uint(par ? x1 : x0);
            uint32_t a1 = __float_as_uint(par ? y1 : y0);
            uint32_t a2 = __float_as_uint(par ? x3 : x2);
            uint32_t a3 = __float_as_uint(par ? y3 : y2);

#pragma unroll
            for (int dn = 0; dn < 8; dn++) {
                float2 b = *(float2*)&VTs[(dn * 8 + g) * AS + n * 8 + 2 * tig];
                mma_tf32(O[dn], a0, a1, a2, a3,
                         __float_as_uint(b.x), __float_as_uint(b.y));
            }
        }
        __syncthreads();
        if (pf) storeKV((kt + 2) % 3);
    }

    // reduce l across the 4 lanes of each row-group, normalize, store
#pragma unroll
    for (int half = 0; half < 2; half++) {
        float l = lacc[half];
        l += __shfl_xor_sync(0xffffffffu, l, 1);
        l += __shfl_xor_sync(0xffffffffu, l, 2);
        lacc[half] = 1.f / l;
    }

    int r0 = q0 + wid * 16 + g;
#pragma unroll
    for (int dn = 0; dn < 8; dn++) {
        int col = h * 64 + dn * 8 + 2 * tig;
        float2 v0 = make_float2(O[dn][0] * lacc[0], O[dn][1] * lacc[0]);
        float2 v1 = make_float2(O[dn][2] * lacc[1], O[dn][3] * lacc[1]);
        *(float2*)(ctx + (size_t)r0 * 256 + col) = v0;
        *(float2*)(ctx + (size_t)(r0 + 8) * 256 + col) = v1;
    }
}

// ---------------- launch ----------------
extern "C" void kernel_launch(void* const* d_in, const int* in_sizes, int n_in,
                              void* d_out, int out_size)
{
    (void)in_sizes; (void)n_in; (void)out_size;
    const float* x_term    = (const float*)d_in[0];
    const float* x_symbol  = (const float*)d_in[1];
    const float* x_var     = (const float*)d_in[2];
    const int*   ha_src    = (const int*)d_in[3];
    const int*   ha_dst    = (const int*)d_in[4];
    const int*   so_src    = (const int*)d_in[5];
    const int*   so_dst    = (const int*)d_in[6];
    const int*   vo_src    = (const int*)d_in[7];
    const int*   vo_dst    = (const int*)d_in[8];
    const float* Wl_rha    = (const float*)d_in[9];
    const float* bl_rha    = (const float*)d_in[10];
    const float* Wr_rha    = (const float*)d_in[11];
    const float* Wl_ha     = (const float*)d_in[12];
    const float* bl_ha     = (const float*)d_in[13];
    const float* Wr_ha     = (const float*)d_in[14];
    const float* Wl_rsym   = (const float*)d_in[15];
    const float* bl_rsym   = (const float*)d_in[16];
    const float* Wr_rsym   = (const float*)d_in[17];
    const float* Wl_var    = (const float*)d_in[18];
    const float* bl_var    = (const float*)d_in[19];
    const float* Wr_var    = (const float*)d_in[20];
    const float* ln_g      = (const float*)d_in[21];
    const float* ln_b      = (const float*)d_in[22];
    const float* in_proj_w = (const float*)d_in[23];
    const float* in_proj_b = (const float*)d_in[24];
    const float* out_proj_w= (const float*)d_in[25];
    const float* out_proj_b= (const float*)d_in[26];
    const float* post_w    = (const float*)d_in[27];
    const float* post_b    = (const float*)d_in[28];
    float* out = (float*)d_out;

    cudaFuncSetAttribute(attn_tc_kernel, cudaFuncAttributeMaxDynamicSharedMemorySize, ATTN_SMEM_BYTES);

    float *pAbig, *pWbig, *pbsum, *pcnt, *ppre, *ptout, *pqkv, *pctx, *pattn;
    cudaGetSymbolAddress((void**)&pAbig, g_Abig);
    cudaGetSymbolAddress((void**)&pWbig, g_Wbig);
    cudaGetSymbolAddress((void**)&pbsum, g_bsum);
    cudaGetSymbolAddress((void**)&pcnt,  g_cnt);
    cudaGetSymbolAddress((void**)&ppre,  g_pre);
    cudaGetSymbolAddress((void**)&ptout, g_tout);
    cudaGetSymbolAddress((void**)&pqkv,  g_qkv);
    cudaGetSymbolAddress((void**)&pctx,  g_ctx);
    cudaGetSymbolAddress((void**)&pattn, g_attn);

    // fused weight-prep + A_big init + cnt zero
    prep_init_kernel<<<(NT * (KBIG / 4) + 255) / 256, 256>>>(x_term,
                                                             Wl_rha, Wl_ha, Wl_rsym, Wl_var,
                                                             Wr_rha, Wr_ha, Wr_rsym, Wr_var,
                                                             bl_rha, bl_ha, bl_rsym, bl_var);
    // scatter + degree counts
    scatter_kernel<<<(ETOT * 32 + 255) / 256, 256>>>(x_term, x_symbol, x_var,
                                                     ha_src, ha_dst, so_src, so_dst, vo_src, vo_dst);

    // conv = (A_big * (1/cnt per block)) @ Wbig^T + bsum + x_term  -> g_pre
    gemm_tc_kernel<<<dim3(H / 64, NT / 128), 256>>>(pAbig, pWbig, pbsum, x_term, pcnt, ppre,
                                                    NT, H, KBIG, 1);
    ln_kernel<<<NT / 8, 256>>>(ppre, ln_g, ln_b, ptout);
    // qkv
    gemm_tc_kernel<<<dim3(3 * H / 64, NT / 128), 256>>>(ptout, in_proj_w, in_proj_b, nullptr, nullptr,
                                                        pqkv, NT, 3 * H, H, 0);
    // attention
    attn_tc_kernel<<<dim3(NT / 128, NH), 256, ATTN_SMEM_BYTES>>>(pqkv, pctx);
    // out_proj
    gemm_tc_kernel<<<dim3(H / 64, NT / 128), 256>>>(pctx, out_proj_w, out_proj_b, nullptr, nullptr,
                                                    pattn, NT, H, H, 0);
    // post: relu(attn @ post_w^T + post_b) + term_out -> d_out
    gemm_tc_kernel<<<dim3(H / 64, NT / 128), 256>>>(pattn, post_w, post_b, ptout, nullptr, out,
                                                    NT, H, H, 2);
}

// round 11
// speedup vs baseline: 3.6983x; 1.4635x over previous
#include <cuda_runtime.h>
#include <cuda_fp16.h>
#include <math.h>
#include <cstdint>

#define NT 4096
#define NS 2048
#define NV 1024
#define H 256
#define NH 4
#define DH 64
#define E1 65536
#define E2 16384
#define E3 32768
#define ETOT (2*E1 + E2 + E3)
#define KBIG 1280   // [agg0|agg1|agg2|agg3|x_term] blocks of 256

// ---------------- scratch (static device globals; no allocation) ----------------
__device__ float g_Abig[NT * KBIG];
__device__ float g_cnt[4 * NT];
__device__ float g_Wbig[H * KBIG];
__device__ float g_bsum[H];
__device__ float g_pre[NT * H];
__device__ float g_tout[NT * H];
__device__ float g_qkv[NT * 3 * H];
__device__ float g_ctx[NT * H];
__device__ float g_attn[NT * H];

// ---------------- fp16 mma.sync helpers ----------------
__device__ __forceinline__ void mma_f16(float* c, uint32_t a0, uint32_t a1, uint32_t a2, uint32_t a3,
                                        uint32_t b0, uint32_t b1)
{
    asm volatile("mma.sync.aligned.m16n8k16.row.col.f32.f16.f16.f32 "
                 "{%0,%1,%2,%3},{%4,%5,%6,%7},{%8,%9},{%0,%1,%2,%3};"
                 : "+f"(c[0]), "+f"(c[1]), "+f"(c[2]), "+f"(c[3])
                 : "r"(a0), "r"(a1), "r"(a2), "r"(a3), "r"(b0), "r"(b1));
}
__device__ __forceinline__ uint32_t h2(float a, float b) {
    __half2 h = __floats2half2_rn(a, b);
    return *(uint32_t*)&h;
}
// Convert 16 consecutive k-floats (one k16 group) into 8 permuted half2 u32:
// pair p_i = (f2i, f2i+1); layout (p0,p4,p1,p5,p2,p6,p3,p7) so that a uint2 at
// offset 2*tig yields {klo(2tig,2tig+1), khi(2tig+8,2tig+9)} = {a0,a2}/{b0,b1}.
__device__ __forceinline__ void cvt_store_group(uint32_t* dst, float4 v0, float4 v1,
                                                float4 v2, float4 v3, float scl)
{
    uint4 u0, u1;
    u0.x = h2(v0.x * scl, v0.y * scl); u0.y = h2(v2.x * scl, v2.y * scl);
    u0.z = h2(v0.z * scl, v0.w * scl); u0.w = h2(v2.z * scl, v2.w * scl);
    u1.x = h2(v1.x * scl, v1.y * scl); u1.y = h2(v3.x * scl, v3.y * scl);
    u1.z = h2(v1.z * scl, v1.w * scl); u1.w = h2(v3.z * scl, v3.w * scl);
    *(uint4*)dst = u0;
    *(uint4*)(dst + 4) = u1;
}

// ---------------- fused prep: Wbig/bsum + A_big init + cnt zero ----------------
__global__ void prep_init_kernel(const float* __restrict__ xt,
                                 const float* __restrict__ Wl0, const float* __restrict__ Wl1,
                                 const float* __restrict__ Wl2, const float* __restrict__ Wl3,
                                 const float* __restrict__ Wr0, const float* __restrict__ Wr1,
                                 const float* __restrict__ Wr2, const float* __restrict__ Wr3,
                                 const float* __restrict__ bl0, const float* __restrict__ bl1,
                                 const float* __restrict__ bl2, const float* __restrict__ bl3)
{
    int idx = blockIdx.x * blockDim.x + threadIdx.x;
    if (idx < NT * (KBIG / 4)) {
        int n = idx / (KBIG / 4), c4 = idx % (KBIG / 4);
        float4 v;
        if (c4 < 256) v = make_float4(0.f, 0.f, 0.f, 0.f);
        else          v = *((const float4*)(xt + (size_t)n * H) + (c4 - 256));
        ((float4*)g_Abig)[idx] = v;
    }
    if (idx < H * KBIG) {
        int h = idx / KBIG, c = idx % KBIG;
        int r = c >> 8, k = c & 255;
        int wi = h * H + k;
        float v;
        if (r == 0)      v = Wl0[wi];
        else if (r == 1) v = Wl1[wi];
        else if (r == 2) v = Wl2[wi];
        else if (r == 3) v = Wl3[wi];
        else             v = Wr0[wi] + Wr1[wi] + Wr2[wi] + Wr3[wi];
        g_Wbig[idx] = v;
    }
    if (idx < 4 * NT) g_cnt[idx] = 0.f;
    if (idx < H) g_bsum[idx] = bl0[idx] + bl1[idx] + bl2[idx] + bl3[idx];
}

// ---------------- scatter-add messages + degree counts (32 thr/edge, MLP=2) ----------------
__global__ void scatter_kernel(const float* __restrict__ xt, const float* __restrict__ xs,
                               const float* __restrict__ xv,
                               const int* __restrict__ ha_src, const int* __restrict__ ha_dst,
                               const int* __restrict__ so_src, const int* __restrict__ so_dst,
                               const int* __restrict__ vo_src, const int* __restrict__ vo_dst)
{
    int idx = blockIdx.x * blockDim.x + threadIdx.x;
    if (idx >= ETOT * 32) return;
    int e = idx >> 5, j = idx & 31;
    int r, s, d; const float* x;
    if (e < E1)               { r = 0; s = ha_dst[e];            d = ha_src[e];            x = xt; }
    else if (e < 2 * E1)      { int q = e - E1;          r = 1; s = ha_src[q]; d = ha_dst[q]; x = xt; }
    else if (e < 2 * E1 + E2) { int q = e - 2 * E1;      r = 2; s = so_dst[q]; d = so_src[q]; x = xs; }
    else                      { int q = e - 2 * E1 - E2; r = 3; s = vo_src[q]; d = vo_dst[q]; x = xv; }
    const float4* src = (const float4*)(x + (size_t)s * H);
    float4 v0 = src[j];
    float4 v1 = src[j + 32];
    float* p = g_Abig + (size_t)d * KBIG + r * H + j * 4;
    asm volatile("red.global.add.v4.f32 [%0], {%1,%2,%3,%4};"
                 :: "l"(p), "f"(v0.x), "f"(v0.y), "f"(v0.z), "f"(v0.w) : "memory");
    asm volatile("red.global.add.v4.f32 [%0], {%1,%2,%3,%4};"
                 :: "l"(p + 128), "f"(v1.x), "f"(v1.y), "f"(v1.z), "f"(v1.w) : "memory");
    if (j == 0) atomicAdd(&g_cnt[r * NT + d], 1.f);
}

// ================= fp16 tensor-core GEMM (3-stage smem pipeline) =================
// C[M,N] = A[M,K] @ W[N,K]^T + bias (+epilogue). cnt!=null => conv mode.
// smem rows hold k-chunk 32 = 2 k16 groups of 8 permuted half2 u32; stride 24 u32.
#define RS 24
#define GSTG2 (192 * RS)
__global__ __launch_bounds__(256, 1)
void gemm_tc_kernel(const float* __restrict__ A, const float* __restrict__ W,
                    const float* __restrict__ bias, const float* __restrict__ resid,
                    const float* __restrict__ cnt,
                    float* __restrict__ C, int M, int N, int K, int mode)
{
    __shared__ __align__(16) uint32_t S[3 * GSTG2];
    int tid = threadIdx.x;
    int lane = tid & 31, wid = tid >> 5;
    int g = lane >> 2, tig = lane & 3;
    int rb = blockIdx.y * 128;
    int cb = blockIdx.x * 64;

    int aRow = tid >> 1;            // A: 2 threads per row, 16 cols (one group) each
    int aGrp = tid & 1;
    int wRow = tid >> 2;            // W: 4 threads per row, 8 cols each
    int wSub = tid & 3;             // grp = wSub>>1, odd = wSub&1

    float inv[4] = {1.f, 1.f, 1.f, 1.f};
    if (cnt) {
#pragma unroll
        for (int r = 0; r < 4; r++)
            inv[r] = 1.f / fmaxf(cnt[r * NT + rb + aRow], 1.f);
    }

    float4 aR[4], wR[2];
    const float* Ap = A + (size_t)(rb + aRow) * K + aGrp * 16;
    const float* Wp = W + (size_t)(cb + wRow) * K + wSub * 8;

    auto loadC = [&](int kc) {
        const float* Ap2 = Ap + kc * 32;
        const float* Wp2 = Wp + kc * 32;
#pragma unroll
        for (int j = 0; j < 4; j++) aR[j] = *(const float4*)(Ap2 + j * 4);
#pragma unroll
        for (int j = 0; j < 2; j++) wR[j] = *(const float4*)(Wp2 + j * 4);
    };
    auto storeC = [&](int kc, int stg) {
        uint32_t* As = S + stg * GSTG2;
        uint32_t* Ws = As + 128 * RS;
        float sc = (cnt && kc < 32) ? inv[kc >> 3] : 1.f;
        cvt_store_group(As + aRow * RS + aGrp * 8, aR[0], aR[1], aR[2], aR[3], sc);
        // W: 8 floats = 4 pairs -> positions {0,2,4,6}+odd within group (wSub>>1)
        uint32_t* wb = Ws + wRow * RS + (wSub >> 1) * 8 + (wSub & 1);
        wb[0] = h2(wR[0].x, wR[0].y);
        wb[2] = h2(wR[0].z, wR[0].w);
        wb[4] = h2(wR[1].x, wR[1].y);
        wb[6] = h2(wR[1].z, wR[1].w);
    };

    float acc[8][4];
#pragma unroll
    for (int n = 0; n < 8; n++)
#pragma unroll
        for (int i = 0; i < 4; i++) acc[n][i] = 0.f;

    int nchunk = K >> 5;
    loadC(0); storeC(0, 0);
    loadC(1); storeC(1, 1);
    __syncthreads();

    int r0 = wid * 16 + g;
    for (int kc = 0; kc < nchunk; kc++) {
        int cur = kc % 3;
        bool pf = (kc + 2) < nchunk;
        if (pf) loadC(kc + 2);

        const uint32_t* As = S + cur * GSTG2;
        const uint32_t* Ws = As + 128 * RS;
#pragma unroll
        for (int ks = 0; ks < 2; ks++) {
            uint2 aA = *(uint2*)&As[r0 * RS + ks * 8 + 2 * tig];
            uint2 aB = *(uint2*)&As[(r0 + 8) * RS + ks * 8 + 2 * tig];
#pragma unroll
            for (int n = 0; n < 8; n++) {
                uint2 b = *(uint2*)&Ws[(n * 8 + g) * RS + ks * 8 + 2 * tig];
                mma_f16(acc[n], aA.x, aB.x, aA.y, aB.y, b.x, b.y);
            }
        }
        __syncthreads();
        if (pf) storeC(kc + 2, (kc + 2) % 3);
    }

    // epilogue (fp32)
    int gr0 = rb + wid * 16 + g;
#pragma unroll
    for (int n = 0; n < 8; n++) {
        int col = cb + n * 8 + 2 * tig;
        float2 bv = *(const float2*)(bias + col);
        float2 v0 = make_float2(acc[n][0] + bv.x, acc[n][1] + bv.y);
        float2 v1 = make_float2(acc[n][2] + bv.x, acc[n][3] + bv.y);
        if (mode == 2) {
            v0.x = fmaxf(v0.x, 0.f); v0.y = fmaxf(v0.y, 0.f);
            v1.x = fmaxf(v1.x, 0.f); v1.y = fmaxf(v1.y, 0.f);
        }
        if (mode >= 1) {
            float2 r0v = *(const float2*)(resid + (size_t)gr0 * N + col);
            float2 r1v = *(const float2*)(resid + (size_t)(gr0 + 8) * N + col);
            v0.x += r0v.x; v0.y += r0v.y; v1.x += r1v.x; v1.y += r1v.y;
        }
        *(float2*)(C + (size_t)gr0 * N + col) = v0;
        *(float2*)(C + (size_t)(gr0 + 8) * N + col) = v1;
    }
}

// ---------------- layernorm ----------------
__global__ __launch_bounds__(256)
void ln_kernel(const float* __restrict__ pre, const float* __restrict__ gam,
               const float* __restrict__ bet, float* __restrict__ out)
{
    int row = blockIdx.x * 8 + (threadIdx.x >> 5);
    int lane = threadIdx.x & 31;
    const float* p = pre + (size_t)row * H + lane * 8;
    float4 a = *(const float4*)p;
    float4 b = *(const float4*)(p + 4);
    float s = a.x + a.y + a.z + a.w + b.x + b.y + b.z + b.w;
#pragma unroll
    for (int off = 16; off; off >>= 1) s += __shfl_xor_sync(0xffffffffu, s, off);
    float mu = s * (1.f / H);
    float dx[8] = {a.x - mu, a.y - mu, a.z - mu, a.w - mu, b.x - mu, b.y - mu, b.z - mu, b.w - mu};
    float vs = 0.f;
#pragma unroll
    for (int i = 0; i < 8; i++) vs += dx[i] * dx[i];
#pragma unroll
    for (int off = 16; off; off >>= 1) vs += __shfl_xor_sync(0xffffffffu, vs, off);
    float rstd = rsqrtf(vs * (1.f / H) + 1e-5f);
    float4 g0 = *(const float4*)(gam + lane * 8);
    float4 g1 = *(const float4*)(gam + lane * 8 + 4);
    float4 b0 = *(const float4*)(bet + lane * 8);
    float4 b1 = *(const float4*)(bet + lane * 8 + 4);
    float4 o0 = make_float4(dx[0] * rstd * g0.x + b0.x, dx[1] * rstd * g0.y + b0.y,
                            dx[2] * rstd * g0.z + b0.z, dx[3] * rstd * g0.w + b0.w);
    float4 o1 = make_float4(dx[4] * rstd * g1.x + b1.x, dx[5] * rstd * g1.y + b1.y,
                            dx[6] * rstd * g1.z + b1.z, dx[7] * rstd * g1.w + b1.w);
    float* q = out + (size_t)row * H + lane * 8;
    *(float4*)q = o0;
    *(float4*)(q + 4) = o1;
}

// ================= fp16 mma.sync flash attention (3-stage KV pipeline) =================
// CTA: 256 threads (8 warps), 128 q-rows, one head. Key tiles of 64, one sync/tile.
// Q pre-scaled by 1/8 so S-mma produces s/8 directly. Fixed-shift softmax.
// smem (u32): Qs[128][QS], per stage: Ks[64][QS] + VT[64][QS] (halves within rows).
#define QS 40
#define QFL (128 * QS)
#define KVSTG (128 * QS)
#define ATTN_SMEM_BYTES ((QFL + 3 * KVSTG) * 4)

__global__ __launch_bounds__(256, 1)
void attn_tc_kernel(const float* __restrict__ qkv, float* __restrict__ ctx)
{
    extern __shared__ __align__(16) uint32_t sm[];
    uint32_t* Qs = sm;

    int tid = threadIdx.x;
    int lane = tid & 31, wid = tid >> 5;
    int g = lane >> 2, tig = lane & 3;
    int h = blockIdx.y;
    int q0 = blockIdx.x * 128;

    // ---- load Q (once), scaled by 1/8, 2 threads per row (2 k16 groups each) ----
    {
        int qRow = tid >> 1;
        int qh = tid & 1;
        const float* qr = qkv + (size_t)(q0 + qRow) * 768 + h * 64 + qh * 32;
        float4 v0 = *(const float4*)(qr + 0),  v1 = *(const float4*)(qr + 4);
        float4 v2 = *(const float4*)(qr + 8),  v3 = *(const float4*)(qr + 12);
        float4 v4 = *(const float4*)(qr + 16), v5 = *(const float4*)(qr + 20);
        float4 v6 = *(const float4*)(qr + 24), v7 = *(const float4*)(qr + 28);
        cvt_store_group(Qs + qRow * QS + qh * 16,     v0, v1, v2, v3, 0.125f);
        cvt_store_group(Qs + qRow * QS + qh * 16 + 8, v4, v5, v6, v7, 0.125f);
    }

    // K/V: 4 threads per K row, 16 cols (one group) each.
    int kRow = tid >> 2;
    int kSub = tid & 3;
    // permuted half-position of this key within its k16 group's 8 half2 slots
    int pk = kRow >> 1;
    int wp = ((pk & 3) << 1) | ((pk >> 2) & 1);
    int hp = (kRow >> 4) * 16 + wp * 2 + (kRow & 1);
    float4 Kbuf[4], Vbuf[4];

    auto loadKV = [&](int kt) {
        const float* kp = qkv + (size_t)(kt * 64 + kRow) * 768 + 256 + h * 64 + kSub * 16;
#pragma unroll
        for (int j = 0; j < 4; j++) Kbuf[j] = *(const float4*)(kp + j * 4);
#pragma unroll
        for (int j = 0; j < 4; j++) Vbuf[j] = *(const float4*)(kp + 256 + j * 4);
    };
    auto storeKV = [&](int stg) {
        uint32_t* Ks = sm + QFL + stg * KVSTG;
        cvt_store_group(Ks + kRow * QS + kSub * 8, Kbuf[0], Kbuf[1], Kbuf[2], Kbuf[3], 1.f);
        __half* VTh = (__half*)(Ks + 64 * QS);
#pragma unroll
        for (int j = 0; j < 4; j++) {
            int d = kSub * 16 + j * 4;
            VTh[(d + 0) * (QS * 2) + hp] = __float2half_rn(Vbuf[j].x);
            VTh[(d + 1) * (QS * 2) + hp] = __float2half_rn(Vbuf[j].y);
            VTh[(d + 2) * (QS * 2) + hp] = __float2half_rn(Vbuf[j].z);
            VTh[(d + 3) * (QS * 2) + hp] = __float2half_rn(Vbuf[j].w);
        }
    };

    float O[8][4];
#pragma unroll
    for (int n = 0; n < 8; n++)
#pragma unroll
        for (int i = 0; i < 4; i++) O[n][i] = 0.f;
    float lacc[2] = {0.f, 0.f};

    loadKV(0); storeKV(0);
    loadKV(1); storeKV(1);
    __syncthreads();

    int qr = wid * 16 + g;
    for (int kt = 0; kt < 64; kt++) {
        int cur = kt % 3;
        bool pf = (kt + 2) < 64;
        if (pf) loadKV(kt + 2);

        const uint32_t* Ks = sm + QFL + cur * KVSTG;
        const uint32_t* VT = Ks + 64 * QS;

        float c[8][4];
#pragma unroll
        for (int n = 0; n < 8; n++)
#pragma unroll
            for (int i = 0; i < 4; i++) c[n][i] = 0.f;

        // S = (Q/8) K^T over d=64 (4 k16 steps)
#pragma unroll
        for (int ks = 0; ks < 4; ks++) {
            uint2 qa = *(uint2*)&Qs[qr * QS + ks * 8 + 2 * tig];
            uint2 qb = *(uint2*)&Qs[(qr + 8) * QS + ks * 8 + 2 * tig];
#pragma unroll
            for (int n = 0; n < 8; n++) {
                uint2 kb = *(uint2*)&Ks[(n * 8 + g) * QS + ks * 8 + 2 * tig];
                mma_f16(c[n], qa.x, qb.x, qa.y, qb.y, kb.x, kb.y);
            }
        }

        // P = exp(S) (clamped), l accumulate; pack per n-pair into fp16 A fragment
        // (fragment-aligned: no shuffles needed), O += P V.
#pragma unroll
        for (int j = 0; j < 4; j++) {
            float p[2][4];
#pragma unroll
            for (int q2 = 0; q2 < 2; q2++) {
                int n = 2 * j + q2;
#pragma unroll
                for (int i = 0; i < 4; i++)
                    p[q2][i] = __expf(fminf(c[n][i], 11.f));
                lacc[0] += p[q2][0] + p[q2][1];
                lacc[1] += p[q2][2] + p[q2][3];
            }
            uint32_t a0 = h2(p[0][0], p[0][1]);
            uint32_t a1 = h2(p[0][2], p[0][3]);
            uint32_t a2 = h2(p[1][0], p[1][1]);
            uint32_t a3 = h2(p[1][2], p[1][3]);
#pragma unroll
            for (int dn = 0; dn < 8; dn++) {
                uint2 vb = *(uint2*)&VT[(dn * 8 + g) * QS + j * 8 + 2 * tig];
                mma_f16(O[dn], a0, a1, a2, a3, vb.x, vb.y);
            }
        }
        __syncthreads();
        if (pf) storeKV((kt + 2) % 3);
    }

    // reduce l across the 4 lanes of each row-group, normalize, store
#pragma unroll
    for (int half = 0; half < 2; half++) {
        float l = lacc[half];
        l += __shfl_xor_sync(0xffffffffu, l, 1);
        l += __shfl_xor_sync(0xffffffffu, l, 2);
        lacc[half] = 1.f / l;
    }

    int r0 = q0 + wid * 16 + g;
#pragma unroll
    for (int dn = 0; dn < 8; dn++) {
        int col = h * 64 + dn * 8 + 2 * tig;
        float2 v0 = make_float2(O[dn][0] * lacc[0], O[dn][1] * lacc[0]);
        float2 v1 = make_float2(O[dn][2] * lacc[1], O[dn][3] * lacc[1]);
        *(float2*)(ctx + (size_t)r0 * 256 + col) = v0;
        *(float2*)(ctx + (size_t)(r0 + 8) * 256 + col) = v1;
    }
}

// ---------------- launch ----------------
extern "C" void kernel_launch(void* const* d_in, const int* in_sizes, int n_in,
                              void* d_out, int out_size)
{
    (void)in_sizes; (void)n_in; (void)out_size;
    const float* x_term    = (const float*)d_in[0];
    const float* x_symbol  = (const float*)d_in[1];
    const float* x_var     = (const float*)d_in[2];
    const int*   ha_src    = (const int*)d_in[3];
    const int*   ha_dst    = (const int*)d_in[4];
    const int*   so_src    = (const int*)d_in[5];
    const int*   so_dst    = (const int*)d_in[6];
    const int*   vo_src    = (const int*)d_in[7];
    const int*   vo_dst    = (const int*)d_in[8];
    const float* Wl_rha    = (const float*)d_in[9];
    const float* bl_rha    = (const float*)d_in[10];
    const float* Wr_rha    = (const float*)d_in[11];
    const float* Wl_ha     = (const float*)d_in[12];
    const float* bl_ha     = (const float*)d_in[13];
    const float* Wr_ha     = (const float*)d_in[14];
    const float* Wl_rsym   = (const float*)d_in[15];
    const float* bl_rsym   = (const float*)d_in[16];
    const float* Wr_rsym   = (const float*)d_in[17];
    const float* Wl_var    = (const float*)d_in[18];
    const float* bl_var    = (const float*)d_in[19];
    const float* Wr_var    = (const float*)d_in[20];
    const float* ln_g      = (const float*)d_in[21];
    const float* ln_b      = (const float*)d_in[22];
    const float* in_proj_w = (const float*)d_in[23];
    const float* in_proj_b = (const float*)d_in[24];
    const float* out_proj_w= (const float*)d_in[25];
    const float* out_proj_b= (const float*)d_in[26];
    const float* post_w    = (const float*)d_in[27];
    const float* post_b    = (const float*)d_in[28];
    float* out = (float*)d_out;

    cudaFuncSetAttribute(attn_tc_kernel, cudaFuncAttributeMaxDynamicSharedMemorySize, ATTN_SMEM_BYTES);

    float *pAbig, *pWbig, *pbsum, *pcnt, *ppre, *ptout, *pqkv, *pctx, *pattn;
    cudaGetSymbolAddress((void**)&pAbig, g_Abig);
    cudaGetSymbolAddress((void**)&pWbig, g_Wbig);
    cudaGetSymbolAddress((void**)&pbsum, g_bsum);
    cudaGetSymbolAddress((void**)&pcnt,  g_cnt);
    cudaGetSymbolAddress((void**)&ppre,  g_pre);
    cudaGetSymbolAddress((void**)&ptout, g_tout);
    cudaGetSymbolAddress((void**)&pqkv,  g_qkv);
    cudaGetSymbolAddress((void**)&pctx,  g_ctx);
    cudaGetSymbolAddress((void**)&pattn, g_attn);

    prep_init_kernel<<<(NT * (KBIG / 4) + 255) / 256, 256>>>(x_term,
                                                             Wl_rha, Wl_ha, Wl_rsym, Wl_var,
                                                             Wr_rha, Wr_ha, Wr_rsym, Wr_var,
                                                             bl_rha, bl_ha, bl_rsym, bl_var);
    scatter_kernel<<<(ETOT * 32 + 255) / 256, 256>>>(x_term, x_symbol, x_var,
                                                     ha_src, ha_dst, so_src, so_dst, vo_src, vo_dst);

    // conv = (A_big * (1/cnt per block)) @ Wbig^T + bsum + x_term  -> g_pre
    gemm_tc_kernel<<<dim3(H / 64, NT / 128), 256>>>(pAbig, pWbig, pbsum, x_term, pcnt, ppre,
                                                    NT, H, KBIG, 1);
    ln_kernel<<<NT / 8, 256>>>(ppre, ln_g, ln_b, ptout);
    gemm_tc_kernel<<<dim3(3 * H / 64, NT / 128), 256>>>(ptout, in_proj_w, in_proj_b, nullptr, nullptr,
                                                        pqkv, NT, 3 * H, H, 0);
    attn_tc_kernel<<<dim3(NT / 128, NH), 256, ATTN_SMEM_BYTES>>>(pqkv, pctx);
    gemm_tc_kernel<<<dim3(H / 64, NT / 128), 256>>>(pctx, out_proj_w, out_proj_b, nullptr, nullptr,
                                                    pattn, NT, H, H, 0);
    gemm_tc_kernel<<<dim3(H / 64, NT / 128), 256>>>(pattn, post_w, post_b, ptout, nullptr, out,
                                                    NT, H, H, 2);
}